// round 1
// baseline (speedup 1.0000x reference)
#include <cuda_runtime.h>

#define BATCH 8
#define NPTS  16384
#define SPTS  2048
#define C1D   128
#define C2D   256
#define K0D   384      // C1+C2
#define OD    256      // both MLP widths
#define M_TOT (BATCH*NPTS)   // 131072
#define BN_EPS 1e-5f

// ---------------- scratch (static device globals; no allocation) ----------------
__device__ float g_p2t[BATCH * SPTS * C2D];          // points2 transposed [b][s][c]
__device__ int   g_idx[M_TOT * 3];
__device__ float g_w  [M_TOT * 3];
__device__ float g_h  [(size_t)M_TOT * K0D];         // concat input  [m][k]
__device__ float g_y0 [(size_t)M_TOT * OD];          // conv0 raw out [m][o]
__device__ float g_y1 [(size_t)M_TOT * OD];          // conv1 raw out [m][o]
__device__ float g_sum0[OD], g_sq0[OD], g_sc0[OD], g_sh0[OD];
__device__ float g_sum1[OD], g_sq1[OD], g_sc1[OD], g_sh1[OD];

// ---------------- kernel 0: zero BN accumulators (graph replays!) --------------
__global__ void k_zero_stats() {
    int t = threadIdx.x;
    if (t < OD) { g_sum0[t] = 0.f; g_sq0[t] = 0.f; g_sum1[t] = 0.f; g_sq1[t] = 0.f; }
}

// ---------------- kernel 1: 3-NN + inverse-distance weights --------------------
__global__ void k_nn3(const float* __restrict__ xyz1, const float* __restrict__ xyz2) {
    __shared__ float sx[SPTS], sy[SPTS], sz[SPTS];
    int b = blockIdx.y;
    const float* x2 = xyz2 + (size_t)b * SPTS * 3;
    for (int i = threadIdx.x; i < SPTS * 3; i += blockDim.x) {
        float v = x2[i];
        int s = i / 3, d = i - 3 * s;
        if (d == 0) sx[s] = v; else if (d == 1) sy[s] = v; else sz[s] = v;
    }
    __syncthreads();

    int n = blockIdx.x * blockDim.x + threadIdx.x;
    const float* p = xyz1 + ((size_t)b * NPTS + n) * 3;
    float px = p[0], py = p[1], pz = p[2];

    float d0 = 1e30f, d1 = 1e30f, d2 = 1e30f;
    int   i0 = 0,     i1 = 0,     i2 = 0;
    #pragma unroll 4
    for (int s = 0; s < SPTS; ++s) {
        float dx = px - sx[s], dy = py - sy[s], dz = pz - sz[s];
        float d = fmaf(dx, dx, fmaf(dy, dy, dz * dz));
        if (d < d2) {
            if (d < d1) {
                d2 = d1; i2 = i1;
                if (d < d0) { d1 = d0; i1 = i0; d0 = d; i0 = s; }
                else        { d1 = d;  i1 = s; }
            } else { d2 = d; i2 = s; }
        }
    }
    d0 = fmaxf(d0, 1e-10f); d1 = fmaxf(d1, 1e-10f); d2 = fmaxf(d2, 1e-10f);
    float w0 = 1.f / d0, w1 = 1.f / d1, w2 = 1.f / d2;
    float inv = 1.f / (w0 + w1 + w2);
    int base = ((b * NPTS) + n) * 3;
    g_idx[base] = i0; g_idx[base + 1] = i1; g_idx[base + 2] = i2;
    g_w[base] = w0 * inv; g_w[base + 1] = w1 * inv; g_w[base + 2] = w2 * inv;
}

// ---------------- kernel 2: transpose points2 [b,c,s] -> [b,s,c] ---------------
__global__ void k_tr_p2(const float* __restrict__ p2) {
    __shared__ float tile[32][33];
    int b = blockIdx.z;
    int c0 = blockIdx.y * 32, s0 = blockIdx.x * 32;
    int tx = threadIdx.x, ty = threadIdx.y;
    #pragma unroll
    for (int i = 0; i < 32; i += 8)
        tile[ty + i][tx] = p2[((size_t)(b * C2D + c0 + ty + i)) * SPTS + s0 + tx];
    __syncthreads();
    #pragma unroll
    for (int i = 0; i < 32; i += 8)
        g_p2t[((size_t)(b * SPTS + s0 + ty + i)) * C2D + c0 + tx] = tile[tx][ty + i];
}

// ---------------- kernel 3: build interp part of h (one warp per point) --------
__global__ void k_interp() {
    int gwarp = (blockIdx.x * blockDim.x + threadIdx.x) >> 5;
    int lane  = threadIdx.x & 31;
    int b = gwarp >> 14;                     // NPTS = 2^14
    int base = gwarp * 3;
    int i0 = g_idx[base], i1 = g_idx[base + 1], i2 = g_idx[base + 2];
    float w0 = g_w[base], w1 = g_w[base + 1], w2 = g_w[base + 2];
    const float4* r0 = (const float4*)(g_p2t + ((size_t)b * SPTS + i0) * C2D);
    const float4* r1 = (const float4*)(g_p2t + ((size_t)b * SPTS + i1) * C2D);
    const float4* r2 = (const float4*)(g_p2t + ((size_t)b * SPTS + i2) * C2D);
    float4* h = (float4*)(g_h + (size_t)gwarp * K0D);
    #pragma unroll
    for (int c = lane; c < C2D / 4; c += 32) {
        float4 a = r0[c], bb = r1[c], cc = r2[c], o;
        o.x = w0 * a.x + w1 * bb.x + w2 * cc.x;
        o.y = w0 * a.y + w1 * bb.y + w2 * cc.y;
        o.z = w0 * a.z + w1 * bb.z + w2 * cc.z;
        o.w = w0 * a.w + w1 * bb.w + w2 * cc.w;
        h[c] = o;
    }
}

// ---------------- kernel 4: points1 [b,c,n] -> h[:, 256+c] ---------------------
__global__ void k_tr_p1(const float* __restrict__ p1) {
    __shared__ float tile[32][33];
    int b = blockIdx.z;
    int c0 = blockIdx.y * 32, n0 = blockIdx.x * 32;
    int tx = threadIdx.x, ty = threadIdx.y;
    #pragma unroll
    for (int i = 0; i < 32; i += 8)
        tile[ty + i][tx] = p1[((size_t)(b * C1D + c0 + ty + i)) * NPTS + n0 + tx];
    __syncthreads();
    #pragma unroll
    for (int i = 0; i < 32; i += 8)
        g_h[((size_t)(b * NPTS + n0 + ty + i)) * K0D + C2D + c0 + tx] = tile[tx][ty + i];
}

// ---------------- SGEMM: C[m,o] = sum_k A[m,k] * W[o,k], + BN-stat epilogue ----
// LAYER 0: A = g_h (raw),             C = g_y0, stats -> g_sum0/g_sq0
// LAYER 1: A = relu(g_y0*sc0+sh0),    C = g_y1, stats -> g_sum1/g_sq1
template <int KDIM, int LAYER>
__global__ __launch_bounds__(256, 2) void k_gemm(const float* __restrict__ W) {
    const int BK = 16;
    __shared__ float As[BK][128];
    __shared__ float Bs[BK][128];
    __shared__ float ssum[128], ssq[128];

    const float* A = (LAYER == 0) ? g_h : g_y0;
    float*       C = (LAYER == 0) ? g_y0 : g_y1;
    float*    gsum = (LAYER == 0) ? g_sum0 : g_sum1;
    float*     gsq = (LAYER == 0) ? g_sq0 : g_sq1;

    int tid = threadIdx.x;
    int tx = tid & 15, ty = tid >> 4;
    int bx = blockIdx.x, by = blockIdx.y;

    float acc[8][8];
    #pragma unroll
    for (int i = 0; i < 8; ++i)
        #pragma unroll
        for (int j = 0; j < 8; ++j) acc[i][j] = 0.f;

    float4 ra[2], rb[2];
    const int KT = KDIM / BK;

    // ---- prologue: load tile 0 into regs ----
    #pragma unroll
    for (int u = 0; u < 2; ++u) {
        int i = tid + u * 256;
        int m = i >> 2, kq = i & 3;
        float4 v = *(const float4*)(A + (size_t)(by * 128 + m) * KDIM + kq * 4);
        if (LAYER == 1) {
            int c = kq * 4;
            float4 s4 = *(const float4*)(g_sc0 + c);
            float4 h4 = *(const float4*)(g_sh0 + c);
            v.x = fmaxf(fmaf(v.x, s4.x, h4.x), 0.f);
            v.y = fmaxf(fmaf(v.y, s4.y, h4.y), 0.f);
            v.z = fmaxf(fmaf(v.z, s4.z, h4.z), 0.f);
            v.w = fmaxf(fmaf(v.w, s4.w, h4.w), 0.f);
        }
        ra[u] = v;
        int o = i >> 2;
        rb[u] = *(const float4*)(W + (size_t)(bx * 128 + o) * KDIM + kq * 4);
    }
    #pragma unroll
    for (int u = 0; u < 2; ++u) {
        int i = tid + u * 256;
        int m = i >> 2, kq = i & 3;
        As[kq * 4 + 0][m] = ra[u].x; As[kq * 4 + 1][m] = ra[u].y;
        As[kq * 4 + 2][m] = ra[u].z; As[kq * 4 + 3][m] = ra[u].w;
        Bs[kq * 4 + 0][m] = rb[u].x; Bs[kq * 4 + 1][m] = rb[u].y;
        Bs[kq * 4 + 2][m] = rb[u].z; Bs[kq * 4 + 3][m] = rb[u].w;
    }
    __syncthreads();

    for (int kt = 0; kt < KT; ++kt) {
        // prefetch next tile into registers
        if (kt + 1 < KT) {
            #pragma unroll
            for (int u = 0; u < 2; ++u) {
                int i = tid + u * 256;
                int m = i >> 2, kq = i & 3;
                int kg = (kt + 1) * BK + kq * 4;
                float4 v = *(const float4*)(A + (size_t)(by * 128 + m) * KDIM + kg);
                if (LAYER == 1) {
                    float4 s4 = *(const float4*)(g_sc0 + kg);
                    float4 h4 = *(const float4*)(g_sh0 + kg);
                    v.x = fmaxf(fmaf(v.x, s4.x, h4.x), 0.f);
                    v.y = fmaxf(fmaf(v.y, s4.y, h4.y), 0.f);
                    v.z = fmaxf(fmaf(v.z, s4.z, h4.z), 0.f);
                    v.w = fmaxf(fmaf(v.w, s4.w, h4.w), 0.f);
                }
                ra[u] = v;
                rb[u] = *(const float4*)(W + (size_t)(bx * 128 + m) * KDIM + kg);
            }
        }
        // compute on current smem tiles
        #pragma unroll
        for (int k = 0; k < BK; ++k) {
            float a[8], bb[8];
            #pragma unroll
            for (int i = 0; i < 8; ++i) a[i] = As[k][ty * 8 + i];
            #pragma unroll
            for (int j = 0; j < 8; ++j) bb[j] = Bs[k][tx * 8 + j];
            #pragma unroll
            for (int i = 0; i < 8; ++i)
                #pragma unroll
                for (int j = 0; j < 8; ++j) acc[i][j] = fmaf(a[i], bb[j], acc[i][j]);
        }
        __syncthreads();
        if (kt + 1 < KT) {
            #pragma unroll
            for (int u = 0; u < 2; ++u) {
                int i = tid + u * 256;
                int m = i >> 2, kq = i & 3;
                As[kq * 4 + 0][m] = ra[u].x; As[kq * 4 + 1][m] = ra[u].y;
                As[kq * 4 + 2][m] = ra[u].z; As[kq * 4 + 3][m] = ra[u].w;
                Bs[kq * 4 + 0][m] = rb[u].x; Bs[kq * 4 + 1][m] = rb[u].y;
                Bs[kq * 4 + 2][m] = rb[u].z; Bs[kq * 4 + 3][m] = rb[u].w;
            }
            __syncthreads();
        }
    }

    // ---- epilogue: per-channel sum / sumsq + C store ----
    if (tid < 128) { ssum[tid] = 0.f; ssq[tid] = 0.f; }
    __syncthreads();
    #pragma unroll
    for (int j = 0; j < 8; ++j) {
        float cs = 0.f, cq = 0.f;
        #pragma unroll
        for (int i = 0; i < 8; ++i) { cs += acc[i][j]; cq = fmaf(acc[i][j], acc[i][j], cq); }
        atomicAdd(&ssum[tx * 8 + j], cs);
        atomicAdd(&ssq [tx * 8 + j], cq);
    }
    #pragma unroll
    for (int i = 0; i < 8; ++i) {
        float4* cp = (float4*)(C + (size_t)(by * 128 + ty * 8 + i) * OD + bx * 128 + tx * 8);
        cp[0] = make_float4(acc[i][0], acc[i][1], acc[i][2], acc[i][3]);
        cp[1] = make_float4(acc[i][4], acc[i][5], acc[i][6], acc[i][7]);
    }
    __syncthreads();
    if (tid < 128) {
        atomicAdd(&gsum[bx * 128 + tid], ssum[tid]);
        atomicAdd(&gsq [bx * 128 + tid], ssq [tid]);
    }
}

// ---------------- finalize BN stats -> per-channel scale / shift ---------------
template <int LAYER>
__global__ void k_fin(const float* __restrict__ g, const float* __restrict__ beta) {
    int o = threadIdx.x;
    float* sum = (LAYER == 0) ? g_sum0 : g_sum1;
    float* sq  = (LAYER == 0) ? g_sq0  : g_sq1;
    float* sc  = (LAYER == 0) ? g_sc0  : g_sc1;
    float* sh  = (LAYER == 0) ? g_sh0  : g_sh1;
    const float invM = 1.f / (float)M_TOT;
    float mean = sum[o] * invM;
    float var  = sq[o] * invM - mean * mean;
    float rstd = rsqrtf(var + BN_EPS);
    float s = g[o] * rstd;
    sc[o] = s;
    sh[o] = beta[o] - mean * s;
}

// ---------------- output: BN1+ReLU fused transpose [m,o] -> [b,o,n] ------------
__global__ void k_out(float* __restrict__ out) {
    __shared__ float tile[32][33];
    int b = blockIdx.z;
    int o0 = blockIdx.y * 32, n0 = blockIdx.x * 32;
    int tx = threadIdx.x, ty = threadIdx.y;
    float sc = g_sc1[o0 + tx], sh = g_sh1[o0 + tx];
    #pragma unroll
    for (int i = 0; i < 32; i += 8) {
        float y = g_y1[((size_t)(b * NPTS + n0 + ty + i)) * OD + o0 + tx];
        tile[ty + i][tx] = fmaxf(fmaf(y, sc, sh), 0.f);
    }
    __syncthreads();
    #pragma unroll
    for (int i = 0; i < 32; i += 8)
        out[((size_t)b * OD + o0 + ty + i) * NPTS + n0 + tx] = tile[tx][ty + i];
}

// ---------------- launch ------------------------------------------------------
extern "C" void kernel_launch(void* const* d_in, const int* in_sizes, int n_in,
                              void* d_out, int out_size) {
    const float* xyz1    = (const float*)d_in[0];
    const float* xyz2    = (const float*)d_in[1];
    const float* points1 = (const float*)d_in[2];
    const float* points2 = (const float*)d_in[3];
    const float* W0      = (const float*)d_in[4];
    const float* g0      = (const float*)d_in[6];
    const float* beta0   = (const float*)d_in[7];
    const float* W1      = (const float*)d_in[8];
    const float* g1      = (const float*)d_in[10];
    const float* beta1   = (const float*)d_in[11];
    float* out = (float*)d_out;

    k_zero_stats<<<1, 256>>>();
    k_nn3<<<dim3(NPTS / 256, BATCH), 256>>>(xyz1, xyz2);
    k_tr_p2<<<dim3(SPTS / 32, C2D / 32, BATCH), dim3(32, 8)>>>(points2);
    k_interp<<<M_TOT / 8, 256>>>();
    k_tr_p1<<<dim3(NPTS / 32, C1D / 32, BATCH), dim3(32, 8)>>>(points1);

    k_gemm<K0D, 0><<<dim3(OD / 128, M_TOT / 128), 256>>>(W0);
    k_fin<0><<<1, OD>>>(g0, beta0);

    k_gemm<OD, 1><<<dim3(OD / 128, M_TOT / 128), 256>>>(W1);
    k_fin<1><<<1, OD>>>(g1, beta1);

    k_out<<<dim3(NPTS / 32, OD / 32, BATCH), dim3(32, 8)>>>(out);
}

// round 9
// speedup vs baseline: 1.6863x; 1.6863x over previous
#include <cuda_runtime.h>
#include <cuda_bf16.h>
#include <cstdint>

#define BATCH 8
#define NPTS  16384
#define SPTS  2048
#define C1D   128
#define C2D   256
#define K0D   384      // C1+C2
#define OD    256      // both MLP widths
#define M_TOT (BATCH*NPTS)   // 131072
#define BN_EPS 1e-5f
#define NSLOT 8

// GEMM tiling: BM=128, BN=128, BK=16, 256 threads, 2-stage, 48KB static smem
#define BM 128
#define BN 128
#define BK 16
#define PITCH 48                       // bytes per smem row (32B data + 16B pad)
#define TILE  (128*PITCH)              // 6144 bytes (one hi or lo tile, A or B)
#define STAGE (4*TILE)                 // Ah,Al,Bh,Bl = 24576
#define SMEMB (2*STAGE)                // 49152 = 48KB

// ---------------- scratch (static device globals; no allocation) ----------------
__device__ __align__(16) float g_p2t[BATCH * SPTS * C2D];
__device__ __align__(16) float g_y0 [(size_t)M_TOT * OD];
__device__ __align__(16) float g_y1 [(size_t)M_TOT * OD];
__device__ __align__(16) __nv_bfloat16 g_a0h[(size_t)M_TOT * K0D];
__device__ __align__(16) __nv_bfloat16 g_a0l[(size_t)M_TOT * K0D];
__device__ __align__(16) __nv_bfloat16 g_a1h[(size_t)M_TOT * OD];
__device__ __align__(16) __nv_bfloat16 g_a1l[(size_t)M_TOT * OD];
__device__ __align__(16) __nv_bfloat16 g_w0h[OD * K0D], g_w0l[OD * K0D];
__device__ __align__(16) __nv_bfloat16 g_w1h[OD * OD],  g_w1l[OD * OD];
__device__ int   g_idx[M_TOT * 3];
__device__ float g_w  [M_TOT * 3];
__device__ float g_sum0[NSLOT * OD], g_sq0[NSLOT * OD];
__device__ float g_sum1[NSLOT * OD], g_sq1[NSLOT * OD];
__device__ __align__(16) float g_sc0[OD];
__device__ __align__(16) float g_sh0[OD];
__device__ __align__(16) float g_sc1[OD];
__device__ __align__(16) float g_sh1[OD];

// ---------------- asm helpers --------------------------------------------------
__device__ __forceinline__ uint32_t s2u(const void* p) {
    uint32_t a;
    asm("{ .reg .u64 t; cvta.to.shared.u64 t, %1; cvt.u32.u64 %0, t; }" : "=r"(a) : "l"(p));
    return a;
}
__device__ __forceinline__ void cp16(uint32_t s, const void* g) {
    asm volatile("cp.async.cg.shared.global [%0], [%1], 16;" :: "r"(s), "l"(g));
}
#define LDX4(r, addr)                                                          \
    asm volatile("ldmatrix.sync.aligned.m8n8.x4.shared.b16 {%0,%1,%2,%3}, [%4];" \
        : "=r"((r)[0]), "=r"((r)[1]), "=r"((r)[2]), "=r"((r)[3]) : "r"(addr))
#define MMA(d, a, b0, b1)                                                      \
    asm volatile("mma.sync.aligned.m16n8k16.row.col.f32.bf16.bf16.f32 "        \
        "{%0,%1,%2,%3}, {%4,%5,%6,%7}, {%8,%9}, {%0,%1,%2,%3};"                \
        : "+f"((d)[0]), "+f"((d)[1]), "+f"((d)[2]), "+f"((d)[3])               \
        : "r"((a)[0]), "r"((a)[1]), "r"((a)[2]), "r"((a)[3]), "r"(b0), "r"(b1))

// ---------------- kernel: zero BN accumulators ---------------------------------
__global__ void k_zero() {
    int t = blockIdx.x * blockDim.x + threadIdx.x;
    if (t < NSLOT * OD) { g_sum0[t] = 0.f; g_sq0[t] = 0.f; g_sum1[t] = 0.f; g_sq1[t] = 0.f; }
}

// ---------------- kernel: split W into bf16 hi/lo ------------------------------
__global__ void k_wsplit(const float* __restrict__ W0, const float* __restrict__ W1) {
    int t = blockIdx.x * blockDim.x + threadIdx.x;
    if (t < OD * K0D) {
        float v = W0[t];
        __nv_bfloat16 h = __float2bfloat16(v);
        g_w0h[t] = h;
        g_w0l[t] = __float2bfloat16(v - __bfloat162float(h));
    }
    if (t < OD * OD) {
        float v = W1[t];
        __nv_bfloat16 h = __float2bfloat16(v);
        g_w1h[t] = h;
        g_w1l[t] = __float2bfloat16(v - __bfloat162float(h));
    }
}

// ---------------- kernel: 3-NN + inverse-distance weights ----------------------
// metric m(s) = |s|^2 - 2 p.s (argmin-equivalent); exact distances for winners.
__global__ void k_nn3(const float* __restrict__ xyz1, const float* __restrict__ xyz2) {
    __shared__ float4 sp[SPTS];
    int b = blockIdx.y;
    const float* x2 = xyz2 + (size_t)b * SPTS * 3;
    for (int i = threadIdx.x; i < SPTS * 3; i += blockDim.x) {
        int s = i / 3, d = i - 3 * s;
        ((float*)&sp[s])[d] = x2[i];
    }
    __syncthreads();
    for (int s = threadIdx.x; s < SPTS; s += blockDim.x) {
        float4 q = sp[s];
        sp[s].w = fmaf(q.x, q.x, fmaf(q.y, q.y, q.z * q.z));
    }
    __syncthreads();

    int n = blockIdx.x * blockDim.x + threadIdx.x;
    const float* p = xyz1 + ((size_t)b * NPTS + n) * 3;
    float px = p[0], py = p[1], pz = p[2];
    float mx = -2.f * px, my = -2.f * py, mz = -2.f * pz;

    float d0 = 1e30f, d1 = 1e30f, d2 = 1e30f;
    int   i0 = 0,     i1 = 0,     i2 = 0;
    #pragma unroll 4
    for (int s = 0; s < SPTS; ++s) {
        float4 q = sp[s];
        float m = fmaf(q.x, mx, fmaf(q.y, my, fmaf(q.z, mz, q.w)));
        if (m < d2) {
            if (m < d1) {
                d2 = d1; i2 = i1;
                if (m < d0) { d1 = d0; i1 = i0; d0 = m; i0 = s; }
                else        { d1 = m;  i1 = s; }
            } else { d2 = m; i2 = s; }
        }
    }
    float t0, t1, t2;
    {
        float4 q = sp[i0]; float dx = px - q.x, dy = py - q.y, dz = pz - q.z;
        t0 = fmaf(dx, dx, fmaf(dy, dy, dz * dz));
        q = sp[i1]; dx = px - q.x; dy = py - q.y; dz = pz - q.z;
        t1 = fmaf(dx, dx, fmaf(dy, dy, dz * dz));
        q = sp[i2]; dx = px - q.x; dy = py - q.y; dz = pz - q.z;
        t2 = fmaf(dx, dx, fmaf(dy, dy, dz * dz));
    }
    t0 = fmaxf(t0, 1e-10f); t1 = fmaxf(t1, 1e-10f); t2 = fmaxf(t2, 1e-10f);
    float w0 = 1.f / t0, w1 = 1.f / t1, w2 = 1.f / t2;
    float inv = 1.f / (w0 + w1 + w2);
    int base = ((b * NPTS) + n) * 3;
    g_idx[base] = i0; g_idx[base + 1] = i1; g_idx[base + 2] = i2;
    g_w[base] = w0 * inv; g_w[base + 1] = w1 * inv; g_w[base + 2] = w2 * inv;
}

// ---------------- transpose points2 [b,c,s] -> [b,s,c] -------------------------
__global__ void k_tr_p2(const float* __restrict__ p2) {
    __shared__ float tile[32][33];
    int b = blockIdx.z;
    int c0 = blockIdx.y * 32, s0 = blockIdx.x * 32;
    int tx = threadIdx.x, ty = threadIdx.y;
    #pragma unroll
    for (int i = 0; i < 32; i += 8)
        tile[ty + i][tx] = p2[((size_t)(b * C2D + c0 + ty + i)) * SPTS + s0 + tx];
    __syncthreads();
    #pragma unroll
    for (int i = 0; i < 32; i += 8)
        g_p2t[((size_t)(b * SPTS + s0 + ty + i)) * C2D + c0 + tx] = tile[tx][ty + i];
}

// ---------------- interp -> a0 cols [0,256) as split bf16 ----------------------
__global__ void k_interp() {
    int gwarp = (blockIdx.x * blockDim.x + threadIdx.x) >> 5;
    int lane  = threadIdx.x & 31;
    int b = gwarp >> 14;
    int base = gwarp * 3;
    int i0 = g_idx[base], i1 = g_idx[base + 1], i2 = g_idx[base + 2];
    float w0 = g_w[base], w1 = g_w[base + 1], w2 = g_w[base + 2];
    const float4* r0 = (const float4*)(g_p2t + ((size_t)b * SPTS + i0) * C2D);
    const float4* r1 = (const float4*)(g_p2t + ((size_t)b * SPTS + i1) * C2D);
    const float4* r2 = (const float4*)(g_p2t + ((size_t)b * SPTS + i2) * C2D);
    uint2* hrow = (uint2*)(g_a0h + (size_t)gwarp * K0D);
    uint2* lrow = (uint2*)(g_a0l + (size_t)gwarp * K0D);
    #pragma unroll
    for (int c = lane; c < C2D / 4; c += 32) {
        float4 a = r0[c], bb = r1[c], cc = r2[c], o;
        o.x = w0 * a.x + w1 * bb.x + w2 * cc.x;
        o.y = w0 * a.y + w1 * bb.y + w2 * cc.y;
        o.z = w0 * a.z + w1 * bb.z + w2 * cc.z;
        o.w = w0 * a.w + w1 * bb.w + w2 * cc.w;
        __nv_bfloat162 h01, h23, l01, l23;
        h01.x = __float2bfloat16(o.x); h01.y = __float2bfloat16(o.y);
        h23.x = __float2bfloat16(o.z); h23.y = __float2bfloat16(o.w);
        l01.x = __float2bfloat16(o.x - __bfloat162float(h01.x));
        l01.y = __float2bfloat16(o.y - __bfloat162float(h01.y));
        l23.x = __float2bfloat16(o.z - __bfloat162float(h23.x));
        l23.y = __float2bfloat16(o.w - __bfloat162float(h23.y));
        uint2 hv, lv;
        hv.x = *(uint32_t*)&h01; hv.y = *(uint32_t*)&h23;
        lv.x = *(uint32_t*)&l01; lv.y = *(uint32_t*)&l23;
        hrow[c] = hv;
        lrow[c] = lv;
    }
}

// ---------------- points1 [b,c,n] -> a0 cols [256,384) split bf16 ---------------
__global__ void k_tr_p1(const float* __restrict__ p1) {
    __shared__ float tile[32][33];
    int b = blockIdx.z;
    int c0 = blockIdx.y * 32, n0 = blockIdx.x * 32;
    int tx = threadIdx.x, ty = threadIdx.y;
    #pragma unroll
    for (int i = 0; i < 32; i += 8)
        tile[ty + i][tx] = p1[((size_t)(b * C1D + c0 + ty + i)) * NPTS + n0 + tx];
    __syncthreads();
    #pragma unroll
    for (int i = 0; i < 32; i += 8) {
        float v = tile[tx][ty + i];
        __nv_bfloat16 h = __float2bfloat16(v);
        size_t off = ((size_t)(b * NPTS + n0 + ty + i)) * K0D + C2D + c0 + tx;
        g_a0h[off] = h;
        g_a0l[off] = __float2bfloat16(v - __bfloat162float(h));
    }
}

// ---------------- y0 -> BN0+ReLU -> split bf16 a1 ------------------------------
__global__ void k_cvt1() {
    size_t t = (size_t)blockIdx.x * blockDim.x + threadIdx.x;   // one float4
    int c = ((int)(t & (OD / 4 - 1))) * 4;
    float4 v = *(const float4*)(g_y0 + t * 4);
    float4 s4 = *(const float4*)(g_sc0 + c);
    float4 h4 = *(const float4*)(g_sh0 + c);
    v.x = fmaxf(fmaf(v.x, s4.x, h4.x), 0.f);
    v.y = fmaxf(fmaf(v.y, s4.y, h4.y), 0.f);
    v.z = fmaxf(fmaf(v.z, s4.z, h4.z), 0.f);
    v.w = fmaxf(fmaf(v.w, s4.w, h4.w), 0.f);
    __nv_bfloat162 h01, h23, l01, l23;
    h01.x = __float2bfloat16(v.x); h01.y = __float2bfloat16(v.y);
    h23.x = __float2bfloat16(v.z); h23.y = __float2bfloat16(v.w);
    l01.x = __float2bfloat16(v.x - __bfloat162float(h01.x));
    l01.y = __float2bfloat16(v.y - __bfloat162float(h01.y));
    l23.x = __float2bfloat16(v.z - __bfloat162float(h23.x));
    l23.y = __float2bfloat16(v.w - __bfloat162float(h23.y));
    uint2 hv, lv;
    hv.x = *(uint32_t*)&h01; hv.y = *(uint32_t*)&h23;
    lv.x = *(uint32_t*)&l01; lv.y = *(uint32_t*)&l23;
    ((uint2*)g_a1h)[t] = hv;
    ((uint2*)g_a1l)[t] = lv;
}

// ---------------- bf16x2-split GEMM via mma.sync (HMMA) -------------------------
// C[m,o] = sum_k A[m,k]*W[o,k]; passes Ah*Bh + Ah*Bl + Al*Bh, fp32 accum.
// All scratch pointers resolved IN DEVICE CODE (never pass __device__ symbols
// as kernel arguments from host — that was the R5/R6 bug).
template <int KDIM>
__device__ __forceinline__ void load_stage(
    uint32_t s0, int bx, int by, int tid, int kt,
    const __nv_bfloat16* Ah, const __nv_bfloat16* Al,
    const __nv_bfloat16* Wh, const __nv_bfloat16* Wl)
{
    int row = tid >> 1, ch = tid & 1;          // 128 rows x 2 16B-chunks
    uint32_t d = s0 + row * PITCH + ch * 16;
    size_t ga = (size_t)(bx * BM + row) * KDIM + kt * BK;
    cp16(d,            (const char*)(Ah + ga) + ch * 16);
    cp16(d + TILE,     (const char*)(Al + ga) + ch * 16);
    size_t gb = (size_t)(by * BN + row) * KDIM + kt * BK;
    cp16(d + 2 * TILE, (const char*)(Wh + gb) + ch * 16);
    cp16(d + 3 * TILE, (const char*)(Wl + gb) + ch * 16);
    asm volatile("cp.async.commit_group;" ::: "memory");
}

template <int LAYER>
__global__ __launch_bounds__(256) void k_gemm()
{
    constexpr int KDIM = (LAYER == 0) ? K0D : OD;
    const __nv_bfloat16* Ah = (LAYER == 0) ? g_a0h : g_a1h;
    const __nv_bfloat16* Al = (LAYER == 0) ? g_a0l : g_a1l;
    const __nv_bfloat16* Wh = (LAYER == 0) ? g_w0h : g_w1h;
    const __nv_bfloat16* Wl = (LAYER == 0) ? g_w0l : g_w1l;
    float* C  = (LAYER == 0) ? g_y0   : g_y1;
    float* GS = (LAYER == 0) ? g_sum0 : g_sum1;
    float* GQ = (LAYER == 0) ? g_sq0  : g_sq1;

    __shared__ __align__(16) char sm[SMEMB];
    uint32_t sb = s2u(sm);
    int tid = threadIdx.x, bx = blockIdx.x, by = blockIdx.y;
    const int KT = KDIM / BK;
    int wid = tid >> 5, lane = tid & 31;
    int wm = wid & 3, wn = wid >> 2;           // 4 M-warps x 2 N-warps

    float acc[2][8][4];
    #pragma unroll
    for (int a = 0; a < 2; ++a)
        #pragma unroll
        for (int b = 0; b < 8; ++b)
            #pragma unroll
            for (int c = 0; c < 4; ++c) acc[a][b][c] = 0.f;

    uint32_t a_off = (wm * 32 + (lane & 15)) * PITCH + ((lane >> 4) << 4);
    uint32_t b_off = (wn * 64 + (lane & 7) + ((lane >> 3) & 1) * 8) * PITCH
                   + ((lane >> 4) << 4);

    load_stage<KDIM>(sb, bx, by, tid, 0, Ah, Al, Wh, Wl);

    for (int kt = 0; kt < KT; ++kt) {
        if (kt + 1 < KT) {
            load_stage<KDIM>(sb + ((kt + 1) & 1) * STAGE, bx, by, tid, kt + 1,
                             Ah, Al, Wh, Wl);
            asm volatile("cp.async.wait_group 1;" ::: "memory");
        } else {
            asm volatile("cp.async.wait_group 0;" ::: "memory");
        }
        __syncthreads();
        uint32_t s0 = sb + (kt & 1) * STAGE;

        uint32_t ah[2][4], al[2][4];
        #pragma unroll
        for (int mf = 0; mf < 2; ++mf) {
            uint32_t aa = s0 + a_off + mf * 16 * PITCH;
            LDX4(ah[mf], aa);
            LDX4(al[mf], aa + TILE);
        }
        #pragma unroll
        for (int g = 0; g < 4; ++g) {
            uint32_t ba = s0 + 2 * TILE + b_off + g * 16 * PITCH;
            uint32_t bh[4], bl[4];
            LDX4(bh, ba);
            LDX4(bl, ba + TILE);
            #pragma unroll
            for (int mf = 0; mf < 2; ++mf) {
                MMA(acc[mf][2 * g],     ah[mf], bh[0], bh[2]);
                MMA(acc[mf][2 * g + 1], ah[mf], bh[1], bh[3]);
                MMA(acc[mf][2 * g],     ah[mf], bl[0], bl[2]);
                MMA(acc[mf][2 * g + 1], ah[mf], bl[1], bl[3]);
                MMA(acc[mf][2 * g],     al[mf], bh[0], bh[2]);
                MMA(acc[mf][2 * g + 1], al[mf], bh[1], bh[3]);
            }
        }
        __syncthreads();
    }

    // ---- epilogue: C store + per-channel stats ----
    float* ssum = (float*)sm;
    float* ssq  = ((float*)sm) + BN;
    if (tid < BN) { ssum[tid] = 0.f; ssq[tid] = 0.f; }
    __syncthreads();

    int rbase = bx * BM + wm * 32 + (lane >> 2);
    int cblk  = by * BN;
    int cbase = wn * 64 + (lane & 3) * 2;
    #pragma unroll
    for (int mf = 0; mf < 2; ++mf)
        #pragma unroll
        for (int g = 0; g < 8; ++g) {
            *(float2*)(C + (size_t)(rbase + mf * 16) * OD + cblk + cbase + g * 8) =
                make_float2(acc[mf][g][0], acc[mf][g][1]);
            *(float2*)(C + (size_t)(rbase + mf * 16 + 8) * OD + cblk + cbase + g * 8) =
                make_float2(acc[mf][g][2], acc[mf][g][3]);
        }

    #pragma unroll
    for (int g = 0; g < 8; ++g)
        #pragma unroll
        for (int e = 0; e < 2; ++e) {
            float v0 = acc[0][g][e], v1 = acc[0][g][e + 2];
            float v2 = acc[1][g][e], v3 = acc[1][g][e + 2];
            float s = v0 + v1 + v2 + v3;
            float q = fmaf(v0, v0, fmaf(v1, v1, fmaf(v2, v2, v3 * v3)));
            #pragma unroll
            for (int m = 4; m < 32; m <<= 1) {
                s += __shfl_xor_sync(0xffffffffu, s, m);
                q += __shfl_xor_sync(0xffffffffu, q, m);
            }
            if ((lane >> 2) == 0) {
                int col = cbase + g * 8 + e;       // within block's 128 cols
                atomicAdd(&ssum[col], s);
                atomicAdd(&ssq[col], q);
            }
        }
    __syncthreads();
    if (tid < BN) {
        int slot = (bx & (NSLOT - 1)) * OD + cblk + tid;
        atomicAdd(&GS[slot], ssum[tid]);
        atomicAdd(&GQ[slot], ssq[tid]);
    }
}

// ---------------- finalize BN stats -> per-channel scale / shift ----------------
template <int LAYER>
__global__ void k_fin(const float* __restrict__ g, const float* __restrict__ beta) {
    int o = threadIdx.x;
    float* SUM = (LAYER == 0) ? g_sum0 : g_sum1;
    float* SQ  = (LAYER == 0) ? g_sq0  : g_sq1;
    float* SC  = (LAYER == 0) ? g_sc0  : g_sc1;
    float* SH  = (LAYER == 0) ? g_sh0  : g_sh1;
    float s = 0.f, q = 0.f;
    #pragma unroll
    for (int k = 0; k < NSLOT; ++k) { s += SUM[k * OD + o]; q += SQ[k * OD + o]; }
    const float invM = 1.f / (float)M_TOT;
    float mean = s * invM;
    float var  = q * invM - mean * mean;
    float rstd = rsqrtf(var + BN_EPS);
    float sc = g[o] * rstd;
    SC[o] = sc;
    SH[o] = beta[o] - mean * sc;
}

// ---------------- output: BN1+ReLU fused transpose [m,o] -> [b,o,n] -------------
__global__ void k_out(float* __restrict__ out) {
    __shared__ float tile[32][33];
    int b = blockIdx.z;
    int o0 = blockIdx.y * 32, n0 = blockIdx.x * 32;
    int tx = threadIdx.x, ty = threadIdx.y;
    float sc = g_sc1[o0 + tx], sh = g_sh1[o0 + tx];
    #pragma unroll
    for (int i = 0; i < 32; i += 8) {
        float y = g_y1[((size_t)(b * NPTS + n0 + ty + i)) * OD + o0 + tx];
        tile[ty + i][tx] = fmaxf(fmaf(y, sc, sh), 0.f);
    }
    __syncthreads();
    #pragma unroll
    for (int i = 0; i < 32; i += 8)
        out[((size_t)b * OD + o0 + ty + i) * NPTS + n0 + tx] = tile[tx][ty + i];
}

// ---------------- launch -------------------------------------------------------
extern "C" void kernel_launch(void* const* d_in, const int* in_sizes, int n_in,
                              void* d_out, int out_size) {
    const float* xyz1    = (const float*)d_in[0];
    const float* xyz2    = (const float*)d_in[1];
    const float* points1 = (const float*)d_in[2];
    const float* points2 = (const float*)d_in[3];
    const float* W0      = (const float*)d_in[4];
    const float* g0      = (const float*)d_in[6];
    const float* beta0   = (const float*)d_in[7];
    const float* W1      = (const float*)d_in[8];
    const float* g1      = (const float*)d_in[10];
    const float* beta1   = (const float*)d_in[11];
    float* out = (float*)d_out;

    k_zero<<<(NSLOT * OD + 255) / 256, 256>>>();
    k_wsplit<<<(OD * K0D + 255) / 256, 256>>>(W0, W1);
    k_nn3<<<dim3(NPTS / 256, BATCH), 256>>>(xyz1, xyz2);
    k_tr_p2<<<dim3(SPTS / 32, C2D / 32, BATCH), dim3(32, 8)>>>(points2);
    k_interp<<<M_TOT / 8, 256>>>();
    k_tr_p1<<<dim3(NPTS / 32, C1D / 32, BATCH), dim3(32, 8)>>>(points1);

    k_gemm<0><<<dim3(M_TOT / BM, OD / BN), 256>>>();
    k_fin<0><<<1, OD>>>(g0, beta0);
    k_cvt1<<<(int)((size_t)M_TOT * OD / 4 / 256), 256>>>();

    k_gemm<1><<<dim3(M_TOT / BM, OD / BN), 256>>>();
    k_fin<1><<<1, OD>>>(g1, beta1);

    k_out<<<dim3(NPTS / 32, OD / 32, BATCH), dim3(32, 8)>>>(out);
}

// round 10
// speedup vs baseline: 1.7089x; 1.0134x over previous
#include <cuda_runtime.h>
#include <cuda_bf16.h>
#include <cstdint>

#define BATCH 8
#define NPTS  16384
#define SPTS  2048
#define C1D   128
#define C2D   256
#define K0D   384      // C1+C2
#define OD    256      // both MLP widths
#define M_TOT (BATCH*NPTS)   // 131072
#define BN_EPS 1e-5f
#define NSLOT 8

// GEMM tiling: BM=128, BN=128, BK=16, 256 threads, 3-stage, 48KB static smem
// Swizzled smem (no padding): PITCH=32B, chunk (16B half) XORed with (row>>2)&1.
#define BM 128
#define BN 128
#define BK 16
#define PITCH 32
#define TILE  (128*PITCH)              // 4096 bytes (one hi or lo tile, A or B)
#define STAGE (4*TILE)                 // Ah,Al,Bh,Bl = 16384
#define SMEMB (3*STAGE)                // 49152 = 48KB, 3 stages

// ---------------- scratch (static device globals; no allocation) ----------------
__device__ __align__(16) float g_p2t[BATCH * SPTS * C2D];
__device__ __align__(16) float g_y0 [(size_t)M_TOT * OD];
__device__ __align__(16) float g_y1 [(size_t)M_TOT * OD];
__device__ __align__(16) __nv_bfloat16 g_a0h[(size_t)M_TOT * K0D];
__device__ __align__(16) __nv_bfloat16 g_a0l[(size_t)M_TOT * K0D];
__device__ __align__(16) __nv_bfloat16 g_a1h[(size_t)M_TOT * OD];
__device__ __align__(16) __nv_bfloat16 g_a1l[(size_t)M_TOT * OD];
__device__ __align__(16) __nv_bfloat16 g_w0h[OD * K0D], g_w0l[OD * K0D];
__device__ __align__(16) __nv_bfloat16 g_w1h[OD * OD],  g_w1l[OD * OD];
__device__ int   g_idx[M_TOT * 3];
__device__ float g_w  [M_TOT * 3];
__device__ float g_sum0[NSLOT * OD], g_sq0[NSLOT * OD];
__device__ float g_sum1[NSLOT * OD], g_sq1[NSLOT * OD];
__device__ __align__(16) float g_sc0[OD];
__device__ __align__(16) float g_sh0[OD];
__device__ __align__(16) float g_sc1[OD];
__device__ __align__(16) float g_sh1[OD];

// ---------------- asm helpers --------------------------------------------------
__device__ __forceinline__ uint32_t s2u(const void* p) {
    uint32_t a;
    asm("{ .reg .u64 t; cvta.to.shared.u64 t, %1; cvt.u32.u64 %0, t; }" : "=r"(a) : "l"(p));
    return a;
}
__device__ __forceinline__ void cp16(uint32_t s, const void* g) {
    asm volatile("cp.async.cg.shared.global [%0], [%1], 16;" :: "r"(s), "l"(g));
}
#define LDX4(r, addr)                                                          \
    asm volatile("ldmatrix.sync.aligned.m8n8.x4.shared.b16 {%0,%1,%2,%3}, [%4];" \
        : "=r"((r)[0]), "=r"((r)[1]), "=r"((r)[2]), "=r"((r)[3]) : "r"(addr))
#define MMA(d, a, b0, b1)                                                      \
    asm volatile("mma.sync.aligned.m16n8k16.row.col.f32.bf16.bf16.f32 "        \
        "{%0,%1,%2,%3}, {%4,%5,%6,%7}, {%8,%9}, {%0,%1,%2,%3};"                \
        : "+f"((d)[0]), "+f"((d)[1]), "+f"((d)[2]), "+f"((d)[3])               \
        : "r"((a)[0]), "r"((a)[1]), "r"((a)[2]), "r"((a)[3]), "r"(b0), "r"(b1))

// ---------------- kernel: zero BN accumulators ---------------------------------
__global__ void k_zero() {
    int t = blockIdx.x * blockDim.x + threadIdx.x;
    if (t < NSLOT * OD) { g_sum0[t] = 0.f; g_sq0[t] = 0.f; g_sum1[t] = 0.f; g_sq1[t] = 0.f; }
}

// ---------------- kernel: split W into bf16 hi/lo ------------------------------
__global__ void k_wsplit(const float* __restrict__ W0, const float* __restrict__ W1) {
    int t = blockIdx.x * blockDim.x + threadIdx.x;
    if (t < OD * K0D) {
        float v = W0[t];
        __nv_bfloat16 h = __float2bfloat16(v);
        g_w0h[t] = h;
        g_w0l[t] = __float2bfloat16(v - __bfloat162float(h));
    }
    if (t < OD * OD) {
        float v = W1[t];
        __nv_bfloat16 h = __float2bfloat16(v);
        g_w1h[t] = h;
        g_w1l[t] = __float2bfloat16(v - __bfloat162float(h));
    }
}

// ---------------- kernel: 3-NN + inverse-distance weights ----------------------
// EXACT reference distance formula (R1 semantics): selection matches top_k.
__global__ void k_nn3(const float* __restrict__ xyz1, const float* __restrict__ xyz2) {
    __shared__ float4 sp[SPTS];
    int b = blockIdx.y;
    const float* x2 = xyz2 + (size_t)b * SPTS * 3;
    for (int i = threadIdx.x; i < SPTS * 3; i += blockDim.x) {
        int s = i / 3, d = i - 3 * s;
        ((float*)&sp[s])[d] = x2[i];
    }
    __syncthreads();

    int n = blockIdx.x * blockDim.x + threadIdx.x;
    const float* p = xyz1 + ((size_t)b * NPTS + n) * 3;
    float px = p[0], py = p[1], pz = p[2];

    float d0 = 1e30f, d1 = 1e30f, d2 = 1e30f;
    int   i0 = 0,     i1 = 0,     i2 = 0;
    #pragma unroll 4
    for (int s = 0; s < SPTS; ++s) {
        float4 q = sp[s];
        float dx = px - q.x, dy = py - q.y, dz = pz - q.z;
        float d = fmaf(dx, dx, fmaf(dy, dy, dz * dz));
        if (d < d2) {
            if (d < d1) {
                d2 = d1; i2 = i1;
                if (d < d0) { d1 = d0; i1 = i0; d0 = d; i0 = s; }
                else        { d1 = d;  i1 = s; }
            } else { d2 = d; i2 = s; }
        }
    }
    d0 = fmaxf(d0, 1e-10f); d1 = fmaxf(d1, 1e-10f); d2 = fmaxf(d2, 1e-10f);
    float w0 = 1.f / d0, w1 = 1.f / d1, w2 = 1.f / d2;
    float inv = 1.f / (w0 + w1 + w2);
    int base = ((b * NPTS) + n) * 3;
    g_idx[base] = i0; g_idx[base + 1] = i1; g_idx[base + 2] = i2;
    g_w[base] = w0 * inv; g_w[base + 1] = w1 * inv; g_w[base + 2] = w2 * inv;
}

// ---------------- transpose points2 [b,c,s] -> [b,s,c] -------------------------
__global__ void k_tr_p2(const float* __restrict__ p2) {
    __shared__ float tile[32][33];
    int b = blockIdx.z;
    int c0 = blockIdx.y * 32, s0 = blockIdx.x * 32;
    int tx = threadIdx.x, ty = threadIdx.y;
    #pragma unroll
    for (int i = 0; i < 32; i += 8)
        tile[ty + i][tx] = p2[((size_t)(b * C2D + c0 + ty + i)) * SPTS + s0 + tx];
    __syncthreads();
    #pragma unroll
    for (int i = 0; i < 32; i += 8)
        g_p2t[((size_t)(b * SPTS + s0 + ty + i)) * C2D + c0 + tx] = tile[tx][ty + i];
}

// ---------------- interp -> a0 cols [0,256) as split bf16 ----------------------
__global__ void k_interp() {
    int gwarp = (blockIdx.x * blockDim.x + threadIdx.x) >> 5;
    int lane  = threadIdx.x & 31;
    int b = gwarp >> 14;
    int base = gwarp * 3;
    int i0 = g_idx[base], i1 = g_idx[base + 1], i2 = g_idx[base + 2];
    float w0 = g_w[base], w1 = g_w[base + 1], w2 = g_w[base + 2];
    const float4* r0 = (const float4*)(g_p2t + ((size_t)b * SPTS + i0) * C2D);
    const float4* r1 = (const float4*)(g_p2t + ((size_t)b * SPTS + i1) * C2D);
    const float4* r2 = (const float4*)(g_p2t + ((size_t)b * SPTS + i2) * C2D);
    uint2* hrow = (uint2*)(g_a0h + (size_t)gwarp * K0D);
    uint2* lrow = (uint2*)(g_a0l + (size_t)gwarp * K0D);
    #pragma unroll
    for (int c = lane; c < C2D / 4; c += 32) {
        float4 a = r0[c], bb = r1[c], cc = r2[c], o;
        o.x = w0 * a.x + w1 * bb.x + w2 * cc.x;
        o.y = w0 * a.y + w1 * bb.y + w2 * cc.y;
        o.z = w0 * a.z + w1 * bb.z + w2 * cc.z;
        o.w = w0 * a.w + w1 * bb.w + w2 * cc.w;
        __nv_bfloat162 h01, h23, l01, l23;
        h01.x = __float2bfloat16(o.x); h01.y = __float2bfloat16(o.y);
        h23.x = __float2bfloat16(o.z); h23.y = __float2bfloat16(o.w);
        l01.x = __float2bfloat16(o.x - __bfloat162float(h01.x));
        l01.y = __float2bfloat16(o.y - __bfloat162float(h01.y));
        l23.x = __float2bfloat16(o.z - __bfloat162float(h23.x));
        l23.y = __float2bfloat16(o.w - __bfloat162float(h23.y));
        uint2 hv, lv;
        hv.x = *(uint32_t*)&h01; hv.y = *(uint32_t*)&h23;
        lv.x = *(uint32_t*)&l01; lv.y = *(uint32_t*)&l23;
        hrow[c] = hv;
        lrow[c] = lv;
    }
}

// ---------------- points1 [b,c,n] -> a0 cols [256,384) split bf16 ---------------
__global__ void k_tr_p1(const float* __restrict__ p1) {
    __shared__ float tile[32][33];
    int b = blockIdx.z;
    int c0 = blockIdx.y * 32, n0 = blockIdx.x * 32;
    int tx = threadIdx.x, ty = threadIdx.y;
    #pragma unroll
    for (int i = 0; i < 32; i += 8)
        tile[ty + i][tx] = p1[((size_t)(b * C1D + c0 + ty + i)) * NPTS + n0 + tx];
    __syncthreads();
    #pragma unroll
    for (int i = 0; i < 32; i += 8) {
        float v = tile[tx][ty + i];
        __nv_bfloat16 h = __float2bfloat16(v);
        size_t off = ((size_t)(b * NPTS + n0 + ty + i)) * K0D + C2D + c0 + tx;
        g_a0h[off] = h;
        g_a0l[off] = __float2bfloat16(v - __bfloat162float(h));
    }
}

// ---------------- y0 -> BN0+ReLU -> split bf16 a1 ------------------------------
__global__ void k_cvt1() {
    size_t t = (size_t)blockIdx.x * blockDim.x + threadIdx.x;   // one float4
    int c = ((int)(t & (OD / 4 - 1))) * 4;
    float4 v = *(const float4*)(g_y0 + t * 4);
    float4 s4 = *(const float4*)(g_sc0 + c);
    float4 h4 = *(const float4*)(g_sh0 + c);
    v.x = fmaxf(fmaf(v.x, s4.x, h4.x), 0.f);
    v.y = fmaxf(fmaf(v.y, s4.y, h4.y), 0.f);
    v.z = fmaxf(fmaf(v.z, s4.z, h4.z), 0.f);
    v.w = fmaxf(fmaf(v.w, s4.w, h4.w), 0.f);
    __nv_bfloat162 h01, h23, l01, l23;
    h01.x = __float2bfloat16(v.x); h01.y = __float2bfloat16(v.y);
    h23.x = __float2bfloat16(v.z); h23.y = __float2bfloat16(v.w);
    l01.x = __float2bfloat16(v.x - __bfloat162float(h01.x));
    l01.y = __float2bfloat16(v.y - __bfloat162float(h01.y));
    l23.x = __float2bfloat16(v.z - __bfloat162float(h23.x));
    l23.y = __float2bfloat16(v.w - __bfloat162float(h23.y));
    uint2 hv, lv;
    hv.x = *(uint32_t*)&h01; hv.y = *(uint32_t*)&h23;
    lv.x = *(uint32_t*)&l01; lv.y = *(uint32_t*)&l23;
    ((uint2*)g_a1h)[t] = hv;
    ((uint2*)g_a1l)[t] = lv;
}

// ---------------- bf16x2-split GEMM via mma.sync (HMMA) -------------------------
// C[m,o] = sum_k A[m,k]*W[o,k]; passes Ah*Bh + Ah*Bl + Al*Bh, fp32 accum.
// Swizzled smem: 16B chunk index XOR (row>>2)&1 -> conflict-free, no padding.
template <int KDIM>
__device__ __forceinline__ void load_stage(
    uint32_t s0, int bx, int by, int tid, int kt,
    const __nv_bfloat16* Ah, const __nv_bfloat16* Al,
    const __nv_bfloat16* Wh, const __nv_bfloat16* Wl)
{
    int row = tid >> 1, ch = tid & 1;          // 128 rows x 2 16B-chunks
    int sw = ch ^ ((row >> 2) & 1);
    uint32_t d = s0 + row * PITCH + sw * 16;
    size_t ga = (size_t)(bx * BM + row) * KDIM + kt * BK;
    cp16(d,            (const char*)(Ah + ga) + ch * 16);
    cp16(d + TILE,     (const char*)(Al + ga) + ch * 16);
    size_t gb = (size_t)(by * BN + row) * KDIM + kt * BK;
    cp16(d + 2 * TILE, (const char*)(Wh + gb) + ch * 16);
    cp16(d + 3 * TILE, (const char*)(Wl + gb) + ch * 16);
    asm volatile("cp.async.commit_group;" ::: "memory");
}

template <int LAYER>
__global__ __launch_bounds__(256) void k_gemm()
{
    constexpr int KDIM = (LAYER == 0) ? K0D : OD;
    const __nv_bfloat16* Ah = (LAYER == 0) ? g_a0h : g_a1h;
    const __nv_bfloat16* Al = (LAYER == 0) ? g_a0l : g_a1l;
    const __nv_bfloat16* Wh = (LAYER == 0) ? g_w0h : g_w1h;
    const __nv_bfloat16* Wl = (LAYER == 0) ? g_w0l : g_w1l;
    float* C  = (LAYER == 0) ? g_y0   : g_y1;
    float* GS = (LAYER == 0) ? g_sum0 : g_sum1;
    float* GQ = (LAYER == 0) ? g_sq0  : g_sq1;

    __shared__ __align__(16) char sm[SMEMB];
    uint32_t sb = s2u(sm);
    int tid = threadIdx.x, bx = blockIdx.x, by = blockIdx.y;
    const int KT = KDIM / BK;
    int wid = tid >> 5, lane = tid & 31;
    int wm = wid & 3, wn = wid >> 2;           // 4 M-warps x 2 N-warps

    float acc[2][8][4];
    #pragma unroll
    for (int a = 0; a < 2; ++a)
        #pragma unroll
        for (int b = 0; b < 8; ++b)
            #pragma unroll
            for (int c = 0; c < 4; ++c) acc[a][b][c] = 0.f;

    // per-lane swizzled chunk bit: rows read are base16 + (lane&15), so
    // (row>>2)&1 == ((lane>>2)&1); logical chunk is (lane>>4).
    uint32_t sw16 = (uint32_t)((((lane >> 4) ^ (lane >> 2)) & 1) << 4);
    uint32_t a_off = (wm * 32 + (lane & 15)) * PITCH + sw16;
    uint32_t b_off = (wn * 64 + (lane & 15)) * PITCH + sw16;

    load_stage<KDIM>(sb, bx, by, tid, 0, Ah, Al, Wh, Wl);
    load_stage<KDIM>(sb + STAGE, bx, by, tid, 1, Ah, Al, Wh, Wl);

    int st = 0;   // stage index = kt % 3
    for (int kt = 0; kt < KT; ++kt) {
        if (kt + 2 < KT) {
            int st2 = st + 2; if (st2 >= 3) st2 -= 3;
            load_stage<KDIM>(sb + st2 * STAGE, bx, by, tid, kt + 2, Ah, Al, Wh, Wl);
            asm volatile("cp.async.wait_group 2;" ::: "memory");
        } else if (kt + 1 < KT) {
            asm volatile("cp.async.wait_group 1;" ::: "memory");
        } else {
            asm volatile("cp.async.wait_group 0;" ::: "memory");
        }
        __syncthreads();
        uint32_t s0 = sb + st * STAGE;

        uint32_t ah[2][4], al[2][4];
        #pragma unroll
        for (int mf = 0; mf < 2; ++mf) {
            uint32_t aa = s0 + a_off + mf * 16 * PITCH;
            LDX4(ah[mf], aa);
            LDX4(al[mf], aa + TILE);
        }
        #pragma unroll
        for (int g = 0; g < 4; ++g) {
            uint32_t ba = s0 + 2 * TILE + b_off + g * 16 * PITCH;
            uint32_t bh[4], bl[4];
            LDX4(bh, ba);
            LDX4(bl, ba + TILE);
            #pragma unroll
            for (int mf = 0; mf < 2; ++mf) {
                MMA(acc[mf][2 * g],     ah[mf], bh[0], bh[2]);
                MMA(acc[mf][2 * g + 1], ah[mf], bh[1], bh[3]);
                MMA(acc[mf][2 * g],     ah[mf], bl[0], bl[2]);
                MMA(acc[mf][2 * g + 1], ah[mf], bl[1], bl[3]);
                MMA(acc[mf][2 * g],     al[mf], bh[0], bh[2]);
                MMA(acc[mf][2 * g + 1], al[mf], bh[1], bh[3]);
            }
        }
        __syncthreads();
        if (++st == 3) st = 0;
    }

    // ---- epilogue: C store + per-channel stats ----
    float* ssum = (float*)sm;
    float* ssq  = ((float*)sm) + BN;
    if (tid < BN) { ssum[tid] = 0.f; ssq[tid] = 0.f; }
    __syncthreads();

    int rbase = bx * BM + wm * 32 + (lane >> 2);
    int cblk  = by * BN;
    int cbase = wn * 64 + (lane & 3) * 2;
    #pragma unroll
    for (int mf = 0; mf < 2; ++mf)
        #pragma unroll
        for (int g = 0; g < 8; ++g) {
            *(float2*)(C + (size_t)(rbase + mf * 16) * OD + cblk + cbase + g * 8) =
                make_float2(acc[mf][g][0], acc[mf][g][1]);
            *(float2*)(C + (size_t)(rbase + mf * 16 + 8) * OD + cblk + cbase + g * 8) =
                make_float2(acc[mf][g][2], acc[mf][g][3]);
        }

    #pragma unroll
    for (int g = 0; g < 8; ++g)
        #pragma unroll
        for (int e = 0; e < 2; ++e) {
            float v0 = acc[0][g][e], v1 = acc[0][g][e + 2];
            float v2 = acc[1][g][e], v3 = acc[1][g][e + 2];
            float s = v0 + v1 + v2 + v3;
            float q = fmaf(v0, v0, fmaf(v1, v1, fmaf(v2, v2, v3 * v3)));
            #pragma unroll
            for (int m = 4; m < 32; m <<= 1) {
                s += __shfl_xor_sync(0xffffffffu, s, m);
                q += __shfl_xor_sync(0xffffffffu, q, m);
            }
            if ((lane >> 2) == 0) {
                int col = cbase + g * 8 + e;       // within block's 128 cols
                atomicAdd(&ssum[col], s);
                atomicAdd(&ssq[col], q);
            }
        }
    __syncthreads();
    if (tid < BN) {
        int slot = (bx & (NSLOT - 1)) * OD + cblk + tid;
        atomicAdd(&GS[slot], ssum[tid]);
        atomicAdd(&GQ[slot], ssq[tid]);
    }
}

// ---------------- finalize BN stats -> per-channel scale / shift ----------------
template <int LAYER>
__global__ void k_fin(const float* __restrict__ g, const float* __restrict__ beta) {
    int o = threadIdx.x;
    float* SUM = (LAYER == 0) ? g_sum0 : g_sum1;
    float* SQ  = (LAYER == 0) ? g_sq0  : g_sq1;
    float* SC  = (LAYER == 0) ? g_sc0  : g_sc1;
    float* SH  = (LAYER == 0) ? g_sh0  : g_sh1;
    float s = 0.f, q = 0.f;
    #pragma unroll
    for (int k = 0; k < NSLOT; ++k) { s += SUM[k * OD + o]; q += SQ[k * OD + o]; }
    const float invM = 1.f / (float)M_TOT;
    float mean = s * invM;
    float var  = q * invM - mean * mean;
    float rstd = rsqrtf(var + BN_EPS);
    float sc = g[o] * rstd;
    SC[o] = sc;
    SH[o] = beta[o] - mean * sc;
}

// ---------------- output: BN1+ReLU fused transpose [m,o] -> [b,o,n] -------------
__global__ void k_out(float* __restrict__ out) {
    __shared__ float tile[32][33];
    int b = blockIdx.z;
    int o0 = blockIdx.y * 32, n0 = blockIdx.x * 32;
    int tx = threadIdx.x, ty = threadIdx.y;
    float sc = g_sc1[o0 + tx], sh = g_sh1[o0 + tx];
    #pragma unroll
    for (int i = 0; i < 32; i += 8) {
        float y = g_y1[((size_t)(b * NPTS + n0 + ty + i)) * OD + o0 + tx];
        tile[ty + i][tx] = fmaxf(fmaf(y, sc, sh), 0.f);
    }
    __syncthreads();
    #pragma unroll
    for (int i = 0; i < 32; i += 8)
        out[((size_t)b * OD + o0 + ty + i) * NPTS + n0 + tx] = tile[tx][ty + i];
}

// ---------------- launch -------------------------------------------------------
extern "C" void kernel_launch(void* const* d_in, const int* in_sizes, int n_in,
                              void* d_out, int out_size) {
    const float* xyz1    = (const float*)d_in[0];
    const float* xyz2    = (const float*)d_in[1];
    const float* points1 = (const float*)d_in[2];
    const float* points2 = (const float*)d_in[3];
    const float* W0      = (const float*)d_in[4];
    const float* g0      = (const float*)d_in[6];
    const float* beta0   = (const float*)d_in[7];
    const float* W1      = (const float*)d_in[8];
    const float* g1      = (const float*)d_in[10];
    const float* beta1   = (const float*)d_in[11];
    float* out = (float*)d_out;

    k_zero<<<(NSLOT * OD + 255) / 256, 256>>>();
    k_wsplit<<<(OD * K0D + 255) / 256, 256>>>(W0, W1);
    k_nn3<<<dim3(NPTS / 256, BATCH), 256>>>(xyz1, xyz2);
    k_tr_p2<<<dim3(SPTS / 32, C2D / 32, BATCH), dim3(32, 8)>>>(points2);
    k_interp<<<M_TOT / 8, 256>>>();
    k_tr_p1<<<dim3(NPTS / 32, C1D / 32, BATCH), dim3(32, 8)>>>(points1);

    k_gemm<0><<<dim3(M_TOT / BM, OD / BN), 256>>>();
    k_fin<0><<<1, OD>>>(g0, beta0);
    k_cvt1<<<(int)((size_t)M_TOT * OD / 4 / 256), 256>>>();

    k_gemm<1><<<dim3(M_TOT / BM, OD / BN), 256>>>();
    k_fin<1><<<1, OD>>>(g1, beta1);

    k_out<<<dim3(NPTS / 32, OD / 32, BATCH), dim3(32, 8)>>>(out);
}

// round 11
// speedup vs baseline: 1.9392x; 1.1348x over previous
#include <cuda_runtime.h>
#include <cuda_fp16.h>
#include <cstdint>

#define BATCH 8
#define NPTS  16384
#define SPTS  2048
#define C1D   128
#define C2D   256
#define K0D   384      // C1+C2
#define OD    256      // both MLP widths
#define M_TOT (BATCH*NPTS)   // 131072
#define BN_EPS 1e-5f
#define NSLOT 8

// GEMM tiling: BM=128, BN=256(=OD), BK=16, 512 threads, 3-stage, 48KB static smem
// fp16 2-pass: C = Ah*W + Al*W  (W rounded once to fp16; dropped A*Wl ~ 2^-12)
#define BM 128
#define BN 256
#define BK 16
#define PITCH 32
#define TILE  (128*PITCH)              // 4096 B
#define STAGE (4*TILE)                 // Ah,Al (2 tiles) + B 256 rows (2 tiles) = 16KB
#define SMEMB (3*STAGE)                // 49152 = 48KB

// ---------------- scratch (static device globals; no allocation) ----------------
__device__ __align__(16) float g_p2t[BATCH * SPTS * C2D];
__device__ __align__(16) float g_y0 [(size_t)M_TOT * OD];
__device__ __align__(16) float g_y1 [(size_t)M_TOT * OD];
__device__ __align__(16) __half g_a0h[(size_t)M_TOT * K0D];
__device__ __align__(16) __half g_a0l[(size_t)M_TOT * K0D];
__device__ __align__(16) __half g_a1h[(size_t)M_TOT * OD];
__device__ __align__(16) __half g_a1l[(size_t)M_TOT * OD];
__device__ __align__(16) __half g_w0h[OD * K0D];
__device__ __align__(16) __half g_w1h[OD * OD];
__device__ int   g_idx[M_TOT * 3];
__device__ float g_w  [M_TOT * 3];
__device__ float g_sum0[NSLOT * OD], g_sq0[NSLOT * OD];
__device__ float g_sum1[NSLOT * OD], g_sq1[NSLOT * OD];
__device__ __align__(16) float g_sc0[OD];
__device__ __align__(16) float g_sh0[OD];
__device__ __align__(16) float g_sc1[OD];
__device__ __align__(16) float g_sh1[OD];

// ---------------- asm helpers --------------------------------------------------
__device__ __forceinline__ uint32_t s2u(const void* p) {
    uint32_t a;
    asm("{ .reg .u64 t; cvta.to.shared.u64 t, %1; cvt.u32.u64 %0, t; }" : "=r"(a) : "l"(p));
    return a;
}
__device__ __forceinline__ void cp16(uint32_t s, const void* g) {
    asm volatile("cp.async.cg.shared.global [%0], [%1], 16;" :: "r"(s), "l"(g));
}
#define LDX4(r, addr)                                                          \
    asm volatile("ldmatrix.sync.aligned.m8n8.x4.shared.b16 {%0,%1,%2,%3}, [%4];" \
        : "=r"((r)[0]), "=r"((r)[1]), "=r"((r)[2]), "=r"((r)[3]) : "r"(addr))
#define MMA(d, a, b0, b1)                                                      \
    asm volatile("mma.sync.aligned.m16n8k16.row.col.f32.f16.f16.f32 "          \
        "{%0,%1,%2,%3}, {%4,%5,%6,%7}, {%8,%9}, {%0,%1,%2,%3};"                \
        : "+f"((d)[0]), "+f"((d)[1]), "+f"((d)[2]), "+f"((d)[3])               \
        : "r"((a)[0]), "r"((a)[1]), "r"((a)[2]), "r"((a)[3]), "r"(b0), "r"(b1))

__device__ __forceinline__ uint2 split_h4(float4 v) {
    // pack hi halves of (x,y,z,w) into .x, lo halves into .y? -> returns (hi01|hi23 packed)
    __half hx = __float2half_rn(v.x), hy = __float2half_rn(v.y);
    __half hz = __float2half_rn(v.z), hw = __float2half_rn(v.w);
    __half2 a, b;
    a.x = hx; a.y = hy; b.x = hz; b.y = hw;
    uint2 r;
    r.x = *(uint32_t*)&a; r.y = *(uint32_t*)&b;
    return r;
}
__device__ __forceinline__ uint2 split_l4(float4 v) {
    __half hx = __float2half_rn(v.x), hy = __float2half_rn(v.y);
    __half hz = __float2half_rn(v.z), hw = __float2half_rn(v.w);
    __half2 a, b;
    a.x = __float2half_rn(v.x - __half2float(hx));
    a.y = __float2half_rn(v.y - __half2float(hy));
    b.x = __float2half_rn(v.z - __half2float(hz));
    b.y = __float2half_rn(v.w - __half2float(hw));
    uint2 r;
    r.x = *(uint32_t*)&a; r.y = *(uint32_t*)&b;
    return r;
}

// ---------------- kernel: zero BN accumulators ---------------------------------
__global__ void k_zero() {
    int t = blockIdx.x * blockDim.x + threadIdx.x;
    if (t < NSLOT * OD) { g_sum0[t] = 0.f; g_sq0[t] = 0.f; g_sum1[t] = 0.f; g_sq1[t] = 0.f; }
}

// ---------------- kernel: round W to fp16 --------------------------------------
__global__ void k_wsplit(const float* __restrict__ W0, const float* __restrict__ W1) {
    int t = blockIdx.x * blockDim.x + threadIdx.x;
    if (t < OD * K0D) g_w0h[t] = __float2half_rn(W0[t]);
    if (t < OD * OD)  g_w1h[t] = __float2half_rn(W1[t]);
}

// ---------------- kernel: 3-NN + inverse-distance weights ----------------------
// EXACT reference distance formula: selection matches top_k.
__global__ void k_nn3(const float* __restrict__ xyz1, const float* __restrict__ xyz2) {
    __shared__ float4 sp[SPTS];
    int b = blockIdx.y;
    const float* x2 = xyz2 + (size_t)b * SPTS * 3;
    for (int i = threadIdx.x; i < SPTS * 3; i += blockDim.x) {
        int s = i / 3, d = i - 3 * s;
        ((float*)&sp[s])[d] = x2[i];
    }
    __syncthreads();

    int n = blockIdx.x * blockDim.x + threadIdx.x;
    const float* p = xyz1 + ((size_t)b * NPTS + n) * 3;
    float px = p[0], py = p[1], pz = p[2];

    float d0 = 1e30f, d1 = 1e30f, d2 = 1e30f;
    int   i0 = 0,     i1 = 0,     i2 = 0;
    #pragma unroll 4
    for (int s = 0; s < SPTS; ++s) {
        float4 q = sp[s];
        float dx = px - q.x, dy = py - q.y, dz = pz - q.z;
        float d = fmaf(dx, dx, fmaf(dy, dy, dz * dz));
        if (d < d2) {
            if (d < d1) {
                d2 = d1; i2 = i1;
                if (d < d0) { d1 = d0; i1 = i0; d0 = d; i0 = s; }
                else        { d1 = d;  i1 = s; }
            } else { d2 = d; i2 = s; }
        }
    }
    d0 = fmaxf(d0, 1e-10f); d1 = fmaxf(d1, 1e-10f); d2 = fmaxf(d2, 1e-10f);
    float w0 = 1.f / d0, w1 = 1.f / d1, w2 = 1.f / d2;
    float inv = 1.f / (w0 + w1 + w2);
    int base = ((b * NPTS) + n) * 3;
    g_idx[base] = i0; g_idx[base + 1] = i1; g_idx[base + 2] = i2;
    g_w[base] = w0 * inv; g_w[base + 1] = w1 * inv; g_w[base + 2] = w2 * inv;
}

// ---------------- transpose points2 [b,c,s] -> [b,s,c] -------------------------
__global__ void k_tr_p2(const float* __restrict__ p2) {
    __shared__ float tile[32][33];
    int b = blockIdx.z;
    int c0 = blockIdx.y * 32, s0 = blockIdx.x * 32;
    int tx = threadIdx.x, ty = threadIdx.y;
    #pragma unroll
    for (int i = 0; i < 32; i += 8)
        tile[ty + i][tx] = p2[((size_t)(b * C2D + c0 + ty + i)) * SPTS + s0 + tx];
    __syncthreads();
    #pragma unroll
    for (int i = 0; i < 32; i += 8)
        g_p2t[((size_t)(b * SPTS + s0 + ty + i)) * C2D + c0 + tx] = tile[tx][ty + i];
}

// ---------------- interp -> a0 cols [0,256) as split fp16 ----------------------
__global__ void k_interp() {
    int gwarp = (blockIdx.x * blockDim.x + threadIdx.x) >> 5;
    int lane  = threadIdx.x & 31;
    int b = gwarp >> 14;
    int base = gwarp * 3;
    int i0 = g_idx[base], i1 = g_idx[base + 1], i2 = g_idx[base + 2];
    float w0 = g_w[base], w1 = g_w[base + 1], w2 = g_w[base + 2];
    const float4* r0 = (const float4*)(g_p2t + ((size_t)b * SPTS + i0) * C2D);
    const float4* r1 = (const float4*)(g_p2t + ((size_t)b * SPTS + i1) * C2D);
    const float4* r2 = (const float4*)(g_p2t + ((size_t)b * SPTS + i2) * C2D);
    uint2* hrow = (uint2*)(g_a0h + (size_t)gwarp * K0D);
    uint2* lrow = (uint2*)(g_a0l + (size_t)gwarp * K0D);
    #pragma unroll
    for (int c = lane; c < C2D / 4; c += 32) {
        float4 a = r0[c], bb = r1[c], cc = r2[c], o;
        o.x = w0 * a.x + w1 * bb.x + w2 * cc.x;
        o.y = w0 * a.y + w1 * bb.y + w2 * cc.y;
        o.z = w0 * a.z + w1 * bb.z + w2 * cc.z;
        o.w = w0 * a.w + w1 * bb.w + w2 * cc.w;
        hrow[c] = split_h4(o);
        lrow[c] = split_l4(o);
    }
}

// ---------------- points1 [b,c,n] -> a0 cols [256,384) split fp16 ---------------
__global__ void k_tr_p1(const float* __restrict__ p1) {
    __shared__ float tile[32][33];
    int b = blockIdx.z;
    int c0 = blockIdx.y * 32, n0 = blockIdx.x * 32;
    int tx = threadIdx.x, ty = threadIdx.y;
    #pragma unroll
    for (int i = 0; i < 32; i += 8)
        tile[ty + i][tx] = p1[((size_t)(b * C1D + c0 + ty + i)) * NPTS + n0 + tx];
    __syncthreads();
    #pragma unroll
    for (int i = 0; i < 32; i += 8) {
        float v = tile[tx][ty + i];
        __half h = __float2half_rn(v);
        size_t off = ((size_t)(b * NPTS + n0 + ty + i)) * K0D + C2D + c0 + tx;
        g_a0h[off] = h;
        g_a0l[off] = __float2half_rn(v - __half2float(h));
    }
}

// ---------------- y0 -> BN0+ReLU -> split fp16 a1 ------------------------------
__global__ void k_cvt1() {
    size_t t = (size_t)blockIdx.x * blockDim.x + threadIdx.x;   // one float4
    int c = ((int)(t & (OD / 4 - 1))) * 4;
    float4 v = *(const float4*)(g_y0 + t * 4);
    float4 s4 = *(const float4*)(g_sc0 + c);
    float4 h4 = *(const float4*)(g_sh0 + c);
    v.x = fmaxf(fmaf(v.x, s4.x, h4.x), 0.f);
    v.y = fmaxf(fmaf(v.y, s4.y, h4.y), 0.f);
    v.z = fmaxf(fmaf(v.z, s4.z, h4.z), 0.f);
    v.w = fmaxf(fmaf(v.w, s4.w, h4.w), 0.f);
    ((uint2*)g_a1h)[t] = split_h4(v);
    ((uint2*)g_a1l)[t] = split_l4(v);
}

// ---------------- fp16 2-pass GEMM via mma.sync (HMMA) --------------------------
// C[m,o] = sum_k A[m,k]*W[o,k];  C = Ah*W + Al*W, fp32 accum.
// BM=128, BN=256(full OD), 512 threads, warps 4M x 4N (32 rows x 64 cols each).
template <int KDIM>
__device__ __forceinline__ void load_stage(
    uint32_t s0, int bx, int tid, int kt,
    const __half* Ah, const __half* Al, const __half* Wh)
{
    {   // A halves: tid<256 -> Ah, tid>=256 -> Al (256 cp16 each)
        int hsel = tid >> 8;
        int q = tid & 255;
        int row = q >> 1, ch = q & 1;
        int sw = ch ^ ((row >> 2) & 1);
        uint32_t d = s0 + hsel * TILE + row * PITCH + sw * 16;
        const __half* src = hsel ? Al : Ah;
        cp16(d, (const char*)(src + (size_t)(bx * BM + row) * KDIM + kt * BK) + ch * 16);
    }
    {   // B: 256 rows x 2 chunks = 512 cp16, one per thread
        int row = tid >> 1, ch = tid & 1;
        int sw = ch ^ ((row >> 2) & 1);
        uint32_t d = s0 + 2 * TILE + row * PITCH + sw * 16;
        cp16(d, (const char*)(Wh + (size_t)row * KDIM + kt * BK) + ch * 16);
    }
    asm volatile("cp.async.commit_group;" ::: "memory");
}

template <int LAYER>
__global__ __launch_bounds__(512) void k_gemm()
{
    constexpr int KDIM = (LAYER == 0) ? K0D : OD;
    const __half* Ah = (LAYER == 0) ? g_a0h : g_a1h;
    const __half* Al = (LAYER == 0) ? g_a0l : g_a1l;
    const __half* Wh = (LAYER == 0) ? g_w0h : g_w1h;
    float* C  = (LAYER == 0) ? g_y0   : g_y1;
    float* GS = (LAYER == 0) ? g_sum0 : g_sum1;
    float* GQ = (LAYER == 0) ? g_sq0  : g_sq1;

    __shared__ __align__(16) char sm[SMEMB];
    uint32_t sb = s2u(sm);
    int tid = threadIdx.x, bx = blockIdx.x;
    const int KT = KDIM / BK;
    int wid = tid >> 5, lane = tid & 31;
    int wm = wid & 3, wn = wid >> 2;           // 4 M-warps x 4 N-warps

    float acc[2][8][4];
    #pragma unroll
    for (int a = 0; a < 2; ++a)
        #pragma unroll
        for (int b = 0; b < 8; ++b)
            #pragma unroll
            for (int c = 0; c < 4; ++c) acc[a][b][c] = 0.f;

    uint32_t sw16 = (uint32_t)((((lane >> 4) ^ (lane >> 2)) & 1) << 4);
    uint32_t a_off = (wm * 32 + (lane & 15)) * PITCH + sw16;
    uint32_t b_off = (wn * 64 + (lane & 15)) * PITCH + sw16;

    load_stage<KDIM>(sb, bx, tid, 0, Ah, Al, Wh);
    load_stage<KDIM>(sb + STAGE, bx, tid, 1, Ah, Al, Wh);

    int st = 0;
    for (int kt = 0; kt < KT; ++kt) {
        if (kt + 2 < KT) {
            int st2 = st + 2; if (st2 >= 3) st2 -= 3;
            load_stage<KDIM>(sb + st2 * STAGE, bx, tid, kt + 2, Ah, Al, Wh);
            asm volatile("cp.async.wait_group 2;" ::: "memory");
        } else if (kt + 1 < KT) {
            asm volatile("cp.async.wait_group 1;" ::: "memory");
        } else {
            asm volatile("cp.async.wait_group 0;" ::: "memory");
        }
        __syncthreads();
        uint32_t s0 = sb + st * STAGE;

        uint32_t ah[2][4], al[2][4];
        #pragma unroll
        for (int mf = 0; mf < 2; ++mf) {
            uint32_t aa = s0 + a_off + mf * 16 * PITCH;
            LDX4(ah[mf], aa);
            LDX4(al[mf], aa + TILE);
        }
        #pragma unroll
        for (int g = 0; g < 4; ++g) {
            uint32_t ba = s0 + 2 * TILE + b_off + g * 16 * PITCH;
            uint32_t bb[4];
            LDX4(bb, ba);
            #pragma unroll
            for (int mf = 0; mf < 2; ++mf) {
                MMA(acc[mf][2 * g],     ah[mf], bb[0], bb[2]);
                MMA(acc[mf][2 * g + 1], ah[mf], bb[1], bb[3]);
                MMA(acc[mf][2 * g],     al[mf], bb[0], bb[2]);
                MMA(acc[mf][2 * g + 1], al[mf], bb[1], bb[3]);
            }
        }
        __syncthreads();
        if (++st == 3) st = 0;
    }

    // ---- epilogue: C store + per-channel stats ----
    float* ssum = (float*)sm;
    float* ssq  = ((float*)sm) + BN;
    if (tid < BN) { ssum[tid] = 0.f; ssq[tid] = 0.f; }
    __syncthreads();

    int rbase = bx * BM + wm * 32 + (lane >> 2);
    int cbase = wn * 64 + (lane & 3) * 2;
    #pragma unroll
    for (int mf = 0; mf < 2; ++mf)
        #pragma unroll
        for (int g = 0; g < 8; ++g) {
            *(float2*)(C + (size_t)(rbase + mf * 16) * OD + cbase + g * 8) =
                make_float2(acc[mf][g][0], acc[mf][g][1]);
            *(float2*)(C + (size_t)(rbase + mf * 16 + 8) * OD + cbase + g * 8) =
                make_float2(acc[mf][g][2], acc[mf][g][3]);
        }

    #pragma unroll
    for (int g = 0; g < 8; ++g)
        #pragma unroll
        for (int e = 0; e < 2; ++e) {
            float v0 = acc[0][g][e], v1 = acc[0][g][e + 2];
            float v2 = acc[1][g][e], v3 = acc[1][g][e + 2];
            float s = v0 + v1 + v2 + v3;
            float q = fmaf(v0, v0, fmaf(v1, v1, fmaf(v2, v2, v3 * v3)));
            #pragma unroll
            for (int m = 4; m < 32; m <<= 1) {
                s += __shfl_xor_sync(0xffffffffu, s, m);
                q += __shfl_xor_sync(0xffffffffu, q, m);
            }
            if ((lane >> 2) == 0) {
                int col = cbase + g * 8 + e;
                atomicAdd(&ssum[col], s);
                atomicAdd(&ssq[col], q);
            }
        }
    __syncthreads();
    if (tid < BN) {
        int slot = (bx & (NSLOT - 1)) * OD + tid;
        atomicAdd(&GS[slot], ssum[tid]);
        atomicAdd(&GQ[slot], ssq[tid]);
    }
}

// ---------------- finalize BN stats -> per-channel scale / shift ----------------
template <int LAYER>
__global__ void k_fin(const float* __restrict__ g, const float* __restrict__ beta) {
    int o = threadIdx.x;
    float* SUM = (LAYER == 0) ? g_sum0 : g_sum1;
    float* SQ  = (LAYER == 0) ? g_sq0  : g_sq1;
    float* SC  = (LAYER == 0) ? g_sc0  : g_sc1;
    float* SH  = (LAYER == 0) ? g_sh0  : g_sh1;
    float s = 0.f, q = 0.f;
    #pragma unroll
    for (int k = 0; k < NSLOT; ++k) { s += SUM[k * OD + o]; q += SQ[k * OD + o]; }
    const float invM = 1.f / (float)M_TOT;
    float mean = s * invM;
    float var  = q * invM - mean * mean;
    float rstd = rsqrtf(var + BN_EPS);
    float sc = g[o] * rstd;
    SC[o] = sc;
    SH[o] = beta[o] - mean * sc;
}

// ---------------- output: BN1+ReLU fused transpose [m,o] -> [b,o,n] -------------
__global__ void k_out(float* __restrict__ out) {
    __shared__ float tile[32][33];
    int b = blockIdx.z;
    int o0 = blockIdx.y * 32, n0 = blockIdx.x * 32;
    int tx = threadIdx.x, ty = threadIdx.y;
    float sc = g_sc1[o0 + tx], sh = g_sh1[o0 + tx];
    #pragma unroll
    for (int i = 0; i < 32; i += 8) {
        float y = g_y1[((size_t)(b * NPTS + n0 + ty + i)) * OD + o0 + tx];
        tile[ty + i][tx] = fmaxf(fmaf(y, sc, sh), 0.f);
    }
    __syncthreads();
    #pragma unroll
    for (int i = 0; i < 32; i += 8)
        out[((size_t)b * OD + o0 + ty + i) * NPTS + n0 + tx] = tile[tx][ty + i];
}

// ---------------- launch -------------------------------------------------------
extern "C" void kernel_launch(void* const* d_in, const int* in_sizes, int n_in,
                              void* d_out, int out_size) {
    const float* xyz1    = (const float*)d_in[0];
    const float* xyz2    = (const float*)d_in[1];
    const float* points1 = (const float*)d_in[2];
    const float* points2 = (const float*)d_in[3];
    const float* W0      = (const float*)d_in[4];
    const float* g0      = (const float*)d_in[6];
    const float* beta0   = (const float*)d_in[7];
    const float* W1      = (const float*)d_in[8];
    const float* g1      = (const float*)d_in[10];
    const float* beta1   = (const float*)d_in[11];
    float* out = (float*)d_out;

    k_zero<<<(NSLOT * OD + 255) / 256, 256>>>();
    k_wsplit<<<(OD * K0D + 255) / 256, 256>>>(W0, W1);
    k_nn3<<<dim3(NPTS / 256, BATCH), 256>>>(xyz1, xyz2);
    k_tr_p2<<<dim3(SPTS / 32, C2D / 32, BATCH), dim3(32, 8)>>>(points2);
    k_interp<<<M_TOT / 8, 256>>>();
    k_tr_p1<<<dim3(NPTS / 32, C1D / 32, BATCH), dim3(32, 8)>>>(points1);

    k_gemm<0><<<M_TOT / BM, 512>>>();
    k_fin<0><<<1, OD>>>(g0, beta0);
    k_cvt1<<<(int)((size_t)M_TOT * OD / 4 / 256), 256>>>();

    k_gemm<1><<<M_TOT / BM, 512>>>();
    k_fin<1><<<1, OD>>>(g1, beta1);

    k_out<<<dim3(NPTS / 32, OD / 32, BATCH), dim3(32, 8)>>>(out);
}

// round 12
// speedup vs baseline: 2.0304x; 1.0471x over previous
#include <cuda_runtime.h>
#include <cuda_fp16.h>
#include <cstdint>

#define BATCH 8
#define NPTS  16384
#define SPTS  2048
#define C1D   128
#define C2D   256
#define K0D   384      // C1+C2
#define OD    256      // both MLP widths
#define M_TOT (BATCH*NPTS)   // 131072
#define BN_EPS 1e-5f
#define NSLOT 8

// GEMM tiling: BM=128, BN=256(=OD), BK=16, 512 threads, 3-stage, 48KB static smem
#define BM 128
#define BN 256
#define BK 16
#define PITCH 32
#define TILE  (128*PITCH)              // 4096 B
#define STAGE (4*TILE)                 // Ah,Al (2 tiles) + B 256 rows (2 tiles) = 16KB
#define SMEMB (3*STAGE)                // 49152 = 48KB

// ---------------- scratch (static device globals; no allocation) ----------------
__device__ __align__(16) float g_p2t[BATCH * SPTS * C2D];
__device__ __align__(16) float g_y0 [(size_t)M_TOT * OD];
__device__ __align__(16) float g_y1 [(size_t)M_TOT * OD];
__device__ __align__(16) __half g_a0h[(size_t)M_TOT * K0D];
__device__ __align__(16) __half g_a0l[(size_t)M_TOT * K0D];
__device__ __align__(16) __half g_w0h[OD * K0D];
__device__ __align__(16) __half g_w1h[OD * OD];
__device__ int   g_idx[M_TOT * 3];
__device__ float g_w  [M_TOT * 3];
__device__ float g_sum0[NSLOT * OD], g_sq0[NSLOT * OD];
__device__ float g_sum1[NSLOT * OD], g_sq1[NSLOT * OD];
__device__ __align__(16) float g_sc0[OD];
__device__ __align__(16) float g_sh0[OD];
__device__ __align__(16) float g_sc1[OD];
__device__ __align__(16) float g_sh1[OD];

// ---------------- asm helpers --------------------------------------------------
__device__ __forceinline__ uint32_t s2u(const void* p) {
    uint32_t a;
    asm("{ .reg .u64 t; cvta.to.shared.u64 t, %1; cvt.u32.u64 %0, t; }" : "=r"(a) : "l"(p));
    return a;
}
__device__ __forceinline__ void cp16(uint32_t s, const void* g) {
    asm volatile("cp.async.cg.shared.global [%0], [%1], 16;" :: "r"(s), "l"(g));
}
#define LDX4(r, addr)                                                          \
    asm volatile("ldmatrix.sync.aligned.m8n8.x4.shared.b16 {%0,%1,%2,%3}, [%4];" \
        : "=r"((r)[0]), "=r"((r)[1]), "=r"((r)[2]), "=r"((r)[3]) : "r"(addr))
#define MMA(d, a, b0, b1)                                                      \
    asm volatile("mma.sync.aligned.m16n8k16.row.col.f32.f16.f16.f32 "          \
        "{%0,%1,%2,%3}, {%4,%5,%6,%7}, {%8,%9}, {%0,%1,%2,%3};"                \
        : "+f"((d)[0]), "+f"((d)[1]), "+f"((d)[2]), "+f"((d)[3])               \
        : "r"((a)[0]), "r"((a)[1]), "r"((a)[2]), "r"((a)[3]), "r"(b0), "r"(b1))

__device__ __forceinline__ uint2 split_h4(float4 v) {
    __half2 a, b;
    a.x = __float2half_rn(v.x); a.y = __float2half_rn(v.y);
    b.x = __float2half_rn(v.z); b.y = __float2half_rn(v.w);
    uint2 r; r.x = *(uint32_t*)&a; r.y = *(uint32_t*)&b;
    return r;
}
__device__ __forceinline__ uint2 split_l4(float4 v) {
    __half hx = __float2half_rn(v.x), hy = __float2half_rn(v.y);
    __half hz = __float2half_rn(v.z), hw = __float2half_rn(v.w);
    __half2 a, b;
    a.x = __float2half_rn(v.x - __half2float(hx));
    a.y = __float2half_rn(v.y - __half2float(hy));
    b.x = __float2half_rn(v.z - __half2float(hz));
    b.y = __float2half_rn(v.w - __half2float(hw));
    uint2 r; r.x = *(uint32_t*)&a; r.y = *(uint32_t*)&b;
    return r;
}

// ---------------- kernel: zero BN accumulators ---------------------------------
__global__ void k_zero() {
    int t = blockIdx.x * blockDim.x + threadIdx.x;
    if (t < NSLOT * OD) { g_sum0[t] = 0.f; g_sq0[t] = 0.f; g_sum1[t] = 0.f; g_sq1[t] = 0.f; }
}

// ---------------- kernel: round W to fp16 --------------------------------------
__global__ void k_wsplit(const float* __restrict__ W0, const float* __restrict__ W1) {
    int t = blockIdx.x * blockDim.x + threadIdx.x;
    if (t < OD * K0D) g_w0h[t] = __float2half_rn(W0[t]);
    if (t < OD * OD)  g_w1h[t] = __float2half_rn(W1[t]);
}

// ---------------- kernel: 3-NN + inverse-distance weights ----------------------
__global__ void k_nn3(const float* __restrict__ xyz1, const float* __restrict__ xyz2) {
    __shared__ float4 sp[SPTS];
    int b = blockIdx.y;
    const float* x2 = xyz2 + (size_t)b * SPTS * 3;
    for (int i = threadIdx.x; i < SPTS * 3; i += blockDim.x) {
        int s = i / 3, d = i - 3 * s;
        ((float*)&sp[s])[d] = x2[i];
    }
    __syncthreads();

    int n = blockIdx.x * blockDim.x + threadIdx.x;
    const float* p = xyz1 + ((size_t)b * NPTS + n) * 3;
    float px = p[0], py = p[1], pz = p[2];

    float d0 = 1e30f, d1 = 1e30f, d2 = 1e30f;
    int   i0 = 0,     i1 = 0,     i2 = 0;
    #pragma unroll 4
    for (int s = 0; s < SPTS; ++s) {
        float4 q = sp[s];
        float dx = px - q.x, dy = py - q.y, dz = pz - q.z;
        float d = fmaf(dx, dx, fmaf(dy, dy, dz * dz));
        if (d < d2) {
            if (d < d1) {
                d2 = d1; i2 = i1;
                if (d < d0) { d1 = d0; i1 = i0; d0 = d; i0 = s; }
                else        { d1 = d;  i1 = s; }
            } else { d2 = d; i2 = s; }
        }
    }
    d0 = fmaxf(d0, 1e-10f); d1 = fmaxf(d1, 1e-10f); d2 = fmaxf(d2, 1e-10f);
    float w0 = 1.f / d0, w1 = 1.f / d1, w2 = 1.f / d2;
    float inv = 1.f / (w0 + w1 + w2);
    int base = ((b * NPTS) + n) * 3;
    g_idx[base] = i0; g_idx[base + 1] = i1; g_idx[base + 2] = i2;
    g_w[base] = w0 * inv; g_w[base + 1] = w1 * inv; g_w[base + 2] = w2 * inv;
}

// ---------------- transpose points2 [b,c,s] -> [b,s,c] -------------------------
__global__ void k_tr_p2(const float* __restrict__ p2) {
    __shared__ float tile[32][33];
    int b = blockIdx.z;
    int c0 = blockIdx.y * 32, s0 = blockIdx.x * 32;
    int tx = threadIdx.x, ty = threadIdx.y;
    #pragma unroll
    for (int i = 0; i < 32; i += 8)
        tile[ty + i][tx] = p2[((size_t)(b * C2D + c0 + ty + i)) * SPTS + s0 + tx];
    __syncthreads();
    #pragma unroll
    for (int i = 0; i < 32; i += 8)
        g_p2t[((size_t)(b * SPTS + s0 + ty + i)) * C2D + c0 + tx] = tile[tx][ty + i];
}

// ---------------- interp -> a0 cols [0,256) as split fp16 ----------------------
__global__ void k_interp() {
    int gwarp = (blockIdx.x * blockDim.x + threadIdx.x) >> 5;
    int lane  = threadIdx.x & 31;
    int b = gwarp >> 14;
    int base = gwarp * 3;
    int i0 = g_idx[base], i1 = g_idx[base + 1], i2 = g_idx[base + 2];
    float w0 = g_w[base], w1 = g_w[base + 1], w2 = g_w[base + 2];
    const float4* r0 = (const float4*)(g_p2t + ((size_t)b * SPTS + i0) * C2D);
    const float4* r1 = (const float4*)(g_p2t + ((size_t)b * SPTS + i1) * C2D);
    const float4* r2 = (const float4*)(g_p2t + ((size_t)b * SPTS + i2) * C2D);
    uint2* hrow = (uint2*)(g_a0h + (size_t)gwarp * K0D);
    uint2* lrow = (uint2*)(g_a0l + (size_t)gwarp * K0D);
    #pragma unroll
    for (int c = lane; c < C2D / 4; c += 32) {
        float4 a = r0[c], bb = r1[c], cc = r2[c], o;
        o.x = w0 * a.x + w1 * bb.x + w2 * cc.x;
        o.y = w0 * a.y + w1 * bb.y + w2 * cc.y;
        o.z = w0 * a.z + w1 * bb.z + w2 * cc.z;
        o.w = w0 * a.w + w1 * bb.w + w2 * cc.w;
        hrow[c] = split_h4(o);
        lrow[c] = split_l4(o);
    }
}

// ---------------- points1 [b,c,n] -> a0 cols [256,384) split fp16 ---------------
__global__ void k_tr_p1(const float* __restrict__ p1) {
    __shared__ float tile[32][33];
    int b = blockIdx.z;
    int c0 = blockIdx.y * 32, n0 = blockIdx.x * 32;
    int tx = threadIdx.x, ty = threadIdx.y;
    #pragma unroll
    for (int i = 0; i < 32; i += 8)
        tile[ty + i][tx] = p1[((size_t)(b * C1D + c0 + ty + i)) * NPTS + n0 + tx];
    __syncthreads();
    #pragma unroll
    for (int i = 0; i < 32; i += 8) {
        float v = tile[tx][ty + i];
        __half h = __float2half_rn(v);
        size_t off = ((size_t)(b * NPTS + n0 + ty + i)) * K0D + C2D + c0 + tx;
        g_a0h[off] = h;
        g_a0l[off] = __float2half_rn(v - __half2float(h));
    }
}

// ---------------- GEMM0: fp16 2-pass, A/B via cp.async -------------------------
__device__ __forceinline__ void load_stage0(
    uint32_t s0, int bx, int tid, int kt)
{
    {   // A halves: tid<256 -> Ah, tid>=256 -> Al (256 cp16 each)
        int hsel = tid >> 8;
        int q = tid & 255;
        int row = q >> 1, ch = q & 1;
        int sw = ch ^ ((row >> 2) & 1);
        uint32_t d = s0 + hsel * TILE + row * PITCH + sw * 16;
        const __half* src = hsel ? g_a0l : g_a0h;
        cp16(d, (const char*)(src + (size_t)(bx * BM + row) * K0D + kt * BK) + ch * 16);
    }
    {   // B: 256 rows x 2 chunks = 512 cp16
        int row = tid >> 1, ch = tid & 1;
        int sw = ch ^ ((row >> 2) & 1);
        uint32_t d = s0 + 2 * TILE + row * PITCH + sw * 16;
        cp16(d, (const char*)(g_w0h + (size_t)row * K0D + kt * BK) + ch * 16);
    }
    asm volatile("cp.async.commit_group;" ::: "memory");
}

// shared epilogue: C store + stats (BN=256 full width)
__device__ __forceinline__ void gemm_epilogue(
    char* sm, int tid, int lane, int wm, int wn, int bx,
    float (*acc)[8][4], float* C, float* GS, float* GQ)
{
    float* ssum = (float*)sm;
    float* ssq  = ((float*)sm) + BN;
    if (tid < BN) { ssum[tid] = 0.f; ssq[tid] = 0.f; }
    __syncthreads();

    int rbase = bx * BM + wm * 32 + (lane >> 2);
    int cbase = wn * 64 + (lane & 3) * 2;
    #pragma unroll
    for (int mf = 0; mf < 2; ++mf)
        #pragma unroll
        for (int g = 0; g < 8; ++g) {
            *(float2*)(C + (size_t)(rbase + mf * 16) * OD + cbase + g * 8) =
                make_float2(acc[mf][g][0], acc[mf][g][1]);
            *(float2*)(C + (size_t)(rbase + mf * 16 + 8) * OD + cbase + g * 8) =
                make_float2(acc[mf][g][2], acc[mf][g][3]);
        }

    #pragma unroll
    for (int g = 0; g < 8; ++g)
        #pragma unroll
        for (int e = 0; e < 2; ++e) {
            float v0 = acc[0][g][e], v1 = acc[0][g][e + 2];
            float v2 = acc[1][g][e], v3 = acc[1][g][e + 2];
            float s = v0 + v1 + v2 + v3;
            float q = fmaf(v0, v0, fmaf(v1, v1, fmaf(v2, v2, v3 * v3)));
            #pragma unroll
            for (int m = 4; m < 32; m <<= 1) {
                s += __shfl_xor_sync(0xffffffffu, s, m);
                q += __shfl_xor_sync(0xffffffffu, q, m);
            }
            if ((lane >> 2) == 0) {
                int col = cbase + g * 8 + e;
                atomicAdd(&ssum[col], s);
                atomicAdd(&ssq[col], q);
            }
        }
    __syncthreads();
    if (tid < BN) {
        int slot = (bx & (NSLOT - 1)) * OD + tid;
        atomicAdd(&GS[slot], ssum[tid]);
        atomicAdd(&GQ[slot], ssq[tid]);
    }
}

#define COMPUTE_TILE(s0)                                                       \
    do {                                                                       \
        uint32_t ah[2][4], al[2][4];                                           \
        _Pragma("unroll")                                                      \
        for (int mf = 0; mf < 2; ++mf) {                                       \
            uint32_t aa = (s0) + a_off + mf * 16 * PITCH;                      \
            LDX4(ah[mf], aa);                                                  \
            LDX4(al[mf], aa + TILE);                                           \
        }                                                                      \
        _Pragma("unroll")                                                      \
        for (int g = 0; g < 4; ++g) {                                          \
            uint32_t ba = (s0) + 2 * TILE + b_off + g * 16 * PITCH;            \
            uint32_t bb[4];                                                    \
            LDX4(bb, ba);                                                      \
            _Pragma("unroll")                                                  \
            for (int mf = 0; mf < 2; ++mf) {                                   \
                MMA(acc[mf][2 * g],     ah[mf], bb[0], bb[2]);                 \
                MMA(acc[mf][2 * g + 1], ah[mf], bb[1], bb[3]);                 \
                MMA(acc[mf][2 * g],     al[mf], bb[0], bb[2]);                 \
                MMA(acc[mf][2 * g + 1], al[mf], bb[1], bb[3]);                 \
            }                                                                  \
        }                                                                      \
    } while (0)

__global__ __launch_bounds__(512) void k_gemm0()
{
    constexpr int KT = K0D / BK;   // 24
    __shared__ __align__(16) char sm[SMEMB];
    uint32_t sb = s2u(sm);
    int tid = threadIdx.x, bx = blockIdx.x;
    int wid = tid >> 5, lane = tid & 31;
    int wm = wid & 3, wn = wid >> 2;

    float acc[2][8][4];
    #pragma unroll
    for (int a = 0; a < 2; ++a)
        #pragma unroll
        for (int b = 0; b < 8; ++b)
            #pragma unroll
            for (int c = 0; c < 4; ++c) acc[a][b][c] = 0.f;

    uint32_t sw16 = (uint32_t)((((lane >> 4) ^ (lane >> 2)) & 1) << 4);
    uint32_t a_off = (wm * 32 + (lane & 15)) * PITCH + sw16;
    uint32_t b_off = (wn * 64 + (lane & 15)) * PITCH + sw16;

    load_stage0(sb, bx, tid, 0);
    load_stage0(sb + STAGE, bx, tid, 1);

    int st = 0;
    for (int kt = 0; kt < KT; ++kt) {
        if (kt + 1 < KT) asm volatile("cp.async.wait_group 1;" ::: "memory");
        else             asm volatile("cp.async.wait_group 0;" ::: "memory");
        __syncthreads();
        if (kt + 2 < KT) {
            int st2 = st + 2; if (st2 >= 3) st2 -= 3;
            load_stage0(sb + st2 * STAGE, bx, tid, kt + 2);
        }
        uint32_t s0 = sb + st * STAGE;
        COMPUTE_TILE(s0);
        if (++st == 3) st = 0;
    }
    __syncthreads();
    gemm_epilogue(sm, tid, lane, wm, wn, bx, acc, g_y0, g_sum0, g_sq0);
}

// ---------------- GEMM1: A = relu(y0*sc0+sh0) fused in-kernel -------------------
// A loaded fp32 via LDG (2 stages ahead), BN0+ReLU+fp16-split in regs, STS to
// the same smem layout; B via 3-stage cp.async.
__global__ __launch_bounds__(512) void k_gemm1()
{
    constexpr int KDIM = OD, KT = KDIM / BK;   // 16
    __shared__ __align__(16) char sm[SMEMB];
    uint32_t sb = s2u(sm);
    int tid = threadIdx.x, bx = blockIdx.x;
    int wid = tid >> 5, lane = tid & 31;
    int wm = wid & 3, wn = wid >> 2;

    float acc[2][8][4];
    #pragma unroll
    for (int a = 0; a < 2; ++a)
        #pragma unroll
        for (int b = 0; b < 8; ++b)
            #pragma unroll
            for (int c = 0; c < 4; ++c) acc[a][b][c] = 0.f;

    uint32_t sw16 = (uint32_t)((((lane >> 4) ^ (lane >> 2)) & 1) << 4);
    uint32_t a_off = (wm * 32 + (lane & 15)) * PITCH + sw16;
    uint32_t b_off = (wn * 64 + (lane & 15)) * PITCH + sw16;

    // A mapping: each thread owns 4 consecutive k of one row per stage
    int arow = tid >> 2, akq = tid & 3;
    const float* ybase = g_y0 + (size_t)(bx * BM + arow) * OD + akq * 4;
    int aswz = (akq >> 1) ^ ((arow >> 2) & 1);
    uint32_t aoffb = (uint32_t)(arow * PITCH + aswz * 16 + (akq & 1) * 8);

    // prologue
    float4 rA0 = *(const float4*)(ybase + 0 * BK);
    float4 rA  = *(const float4*)(ybase + 1 * BK);
    {   // BN+ReLU+split+STS stage 0
        int c = 0 * BK + akq * 4;
        float4 s4 = *(const float4*)(g_sc0 + c);
        float4 h4 = *(const float4*)(g_sh0 + c);
        rA0.x = fmaxf(fmaf(rA0.x, s4.x, h4.x), 0.f);
        rA0.y = fmaxf(fmaf(rA0.y, s4.y, h4.y), 0.f);
        rA0.z = fmaxf(fmaf(rA0.z, s4.z, h4.z), 0.f);
        rA0.w = fmaxf(fmaf(rA0.w, s4.w, h4.w), 0.f);
        *(uint2*)(sm + aoffb)        = split_h4(rA0);
        *(uint2*)(sm + TILE + aoffb) = split_l4(rA0);
    }
    {   // B stages 0,1 via cp.async
        int row = tid >> 1, ch = tid & 1;
        int sw = ch ^ ((row >> 2) & 1);
        uint32_t d = sb + 2 * TILE + row * PITCH + sw * 16;
        cp16(d, (const char*)(g_w1h + (size_t)row * KDIM + 0 * BK) + ch * 16);
        asm volatile("cp.async.commit_group;" ::: "memory");
        cp16(d + STAGE, (const char*)(g_w1h + (size_t)row * KDIM + 1 * BK) + ch * 16);
        asm volatile("cp.async.commit_group;" ::: "memory");
    }

    int st = 0;
    for (int kt = 0; kt < KT; ++kt) {
        if (kt + 1 < KT) asm volatile("cp.async.wait_group 1;" ::: "memory");
        else             asm volatile("cp.async.wait_group 0;" ::: "memory");
        __syncthreads();

        if (kt + 2 < KT) {
            int st2 = st + 2; if (st2 >= 3) st2 -= 3;
            {   // B prefetch kt+2
                int row = tid >> 1, ch = tid & 1;
                int sw = ch ^ ((row >> 2) & 1);
                cp16(sb + st2 * STAGE + 2 * TILE + row * PITCH + sw * 16,
                     (const char*)(g_w1h + (size_t)row * KDIM + (kt + 2) * BK) + ch * 16);
                asm volatile("cp.async.commit_group;" ::: "memory");
            }
            float4 t = *(const float4*)(ybase + (kt + 2) * BK);   // LDG A[kt+2]
            // STS A[kt+1]
            int st1 = st + 1; if (st1 >= 3) st1 -= 3;
            int c = (kt + 1) * BK + akq * 4;
            float4 s4 = *(const float4*)(g_sc0 + c);
            float4 h4 = *(const float4*)(g_sh0 + c);
            rA.x = fmaxf(fmaf(rA.x, s4.x, h4.x), 0.f);
            rA.y = fmaxf(fmaf(rA.y, s4.y, h4.y), 0.f);
            rA.z = fmaxf(fmaf(rA.z, s4.z, h4.z), 0.f);
            rA.w = fmaxf(fmaf(rA.w, s4.w, h4.w), 0.f);
            *(uint2*)(sm + st1 * STAGE + aoffb)        = split_h4(rA);
            *(uint2*)(sm + st1 * STAGE + TILE + aoffb) = split_l4(rA);
            rA = t;
        } else if (kt + 1 < KT) {
            int st1 = st + 1; if (st1 >= 3) st1 -= 3;
            int c = (kt + 1) * BK + akq * 4;
            float4 s4 = *(const float4*)(g_sc0 + c);
            float4 h4 = *(const float4*)(g_sh0 + c);
            rA.x = fmaxf(fmaf(rA.x, s4.x, h4.x), 0.f);
            rA.y = fmaxf(fmaf(rA.y, s4.y, h4.y), 0.f);
            rA.z = fmaxf(fmaf(rA.z, s4.z, h4.z), 0.f);
            rA.w = fmaxf(fmaf(rA.w, s4.w, h4.w), 0.f);
            *(uint2*)(sm + st1 * STAGE + aoffb)        = split_h4(rA);
            *(uint2*)(sm + st1 * STAGE + TILE + aoffb) = split_l4(rA);
        }

        uint32_t s0 = sb + st * STAGE;
        COMPUTE_TILE(s0);
        if (++st == 3) st = 0;
    }
    __syncthreads();
    gemm_epilogue(sm, tid, lane, wm, wn, bx, acc, g_y1, g_sum1, g_sq1);
}

// ---------------- finalize BN stats -> per-channel scale / shift ----------------
template <int LAYER>
__global__ void k_fin(const float* __restrict__ g, const float* __restrict__ beta) {
    int o = threadIdx.x;
    float* SUM = (LAYER == 0) ? g_sum0 : g_sum1;
    float* SQ  = (LAYER == 0) ? g_sq0  : g_sq1;
    float* SC  = (LAYER == 0) ? g_sc0  : g_sc1;
    float* SH  = (LAYER == 0) ? g_sh0  : g_sh1;
    float s = 0.f, q = 0.f;
    #pragma unroll
    for (int k = 0; k < NSLOT; ++k) { s += SUM[k * OD + o]; q += SQ[k * OD + o]; }
    const float invM = 1.f / (float)M_TOT;
    float mean = s * invM;
    float var  = q * invM - mean * mean;
    float rstd = rsqrtf(var + BN_EPS);
    float sc = g[o] * rstd;
    SC[o] = sc;
    SH[o] = beta[o] - mean * sc;
}

// ---------------- output: BN1+ReLU fused transpose [m,o] -> [b,o,n] -------------
__global__ void k_out(float* __restrict__ out) {
    __shared__ float tile[32][33];
    int b = blockIdx.z;
    int o0 = blockIdx.y * 32, n0 = blockIdx.x * 32;
    int tx = threadIdx.x, ty = threadIdx.y;
    float sc = g_sc1[o0 + tx], sh = g_sh1[o0 + tx];
    #pragma unroll
    for (int i = 0; i < 32; i += 8) {
        float y = g_y1[((size_t)(b * NPTS + n0 + ty + i)) * OD + o0 + tx];
        tile[ty + i][tx] = fmaxf(fmaf(y, sc, sh), 0.f);
    }
    __syncthreads();
    #pragma unroll
    for (int i = 0; i < 32; i += 8)
        out[((size_t)b * OD + o0 + ty + i) * NPTS + n0 + tx] = tile[tx][ty + i];
}

// ---------------- launch -------------------------------------------------------
extern "C" void kernel_launch(void* const* d_in, const int* in_sizes, int n_in,
                              void* d_out, int out_size) {
    const float* xyz1    = (const float*)d_in[0];
    const float* xyz2    = (const float*)d_in[1];
    const float* points1 = (const float*)d_in[2];
    const float* points2 = (const float*)d_in[3];
    const float* W0      = (const float*)d_in[4];
    const float* g0      = (const float*)d_in[6];
    const float* beta0   = (const float*)d_in[7];
    const float* W1      = (const float*)d_in[8];
    const float* g1      = (const float*)d_in[10];
    const float* beta1   = (const float*)d_in[11];
    float* out = (float*)d_out;

    k_zero<<<(NSLOT * OD + 255) / 256, 256>>>();
    k_wsplit<<<(OD * K0D + 255) / 256, 256>>>(W0, W1);
    k_nn3<<<dim3(NPTS / 256, BATCH), 256>>>(xyz1, xyz2);
    k_tr_p2<<<dim3(SPTS / 32, C2D / 32, BATCH), dim3(32, 8)>>>(points2);
    k_interp<<<M_TOT / 8, 256>>>();
    k_tr_p1<<<dim3(NPTS / 32, C1D / 32, BATCH), dim3(32, 8)>>>(points1);

    k_gemm0<<<M_TOT / BM, 512>>>();
    k_fin<0><<<1, OD>>>(g0, beta0);

    k_gemm1<<<M_TOT / BM, 512>>>();
    k_fin<1><<<1, OD>>>(g1, beta1);

    k_out<<<dim3(NPTS / 32, OD / 32, BATCH), dim3(32, 8)>>>(out);
}